// round 8
// baseline (speedup 1.0000x reference)
#include <cuda_runtime.h>
#include <cuda_bf16.h>
#include <cstdint>

#define B_  4
#define S_  1024
#define D_  1024
#define H_  16
#define HD_ 64
#define M_  (B_*S_)

// ---------------- scratch (static __device__, no allocation) ----------------
__device__ float g_attn_fb[(size_t)B_*H_*S_*S_];
__device__ __nv_bfloat16 g_xhi[(size_t)M_*D_];
__device__ __nv_bfloat16 g_xlo[(size_t)M_*D_];
__device__ __nv_bfloat16 g_whi[(size_t)D_*D_];
__device__ __nv_bfloat16 g_wlo[(size_t)D_*D_];
__device__ __nv_bfloat16 g_qh[(size_t)B_*H_*S_*HD_];
__device__ __nv_bfloat16 g_ql[(size_t)B_*H_*S_*HD_];
__device__ __nv_bfloat16 g_kh[(size_t)B_*H_*S_*HD_];
__device__ __nv_bfloat16 g_kl[(size_t)B_*H_*S_*HD_];
__device__ __nv_bfloat16 g_vh[(size_t)B_*H_*S_*HD_];
__device__ __nv_bfloat16 g_vl[(size_t)B_*H_*S_*HD_];

// ================= arch-neutral PTX helpers (sm_80-era only) ================
__device__ __forceinline__ uint32_t smem_u32(const void* p) {
    uint32_t a;
    asm("{ .reg .u64 t; cvta.to.shared.u64 t, %1; cvt.u32.u64 %0, t; }" : "=r"(a) : "l"(p));
    return a;
}
__device__ __forceinline__ void cp_async16(uint32_t sdst, const void* gsrc) {
    asm volatile("cp.async.cg.shared.global [%0], [%1], 16;" :: "r"(sdst), "l"(gsrc) : "memory");
}
__device__ __forceinline__ void cp_commit() {
    asm volatile("cp.async.commit_group;" ::: "memory");
}
template<int N>
__device__ __forceinline__ void cp_wait() {
    asm volatile("cp.async.wait_group %0;" :: "n"(N) : "memory");
}
__device__ __forceinline__ void ldm_x4(uint32_t a, uint32_t& r0, uint32_t& r1,
                                       uint32_t& r2, uint32_t& r3) {
    asm volatile("ldmatrix.sync.aligned.m8n8.x4.shared.b16 {%0,%1,%2,%3}, [%4];"
        : "=r"(r0), "=r"(r1), "=r"(r2), "=r"(r3) : "r"(a));
}
__device__ __forceinline__ void ldm_x4_t(uint32_t a, uint32_t& r0, uint32_t& r1,
                                         uint32_t& r2, uint32_t& r3) {
    asm volatile("ldmatrix.sync.aligned.m8n8.x4.trans.shared.b16 {%0,%1,%2,%3}, [%4];"
        : "=r"(r0), "=r"(r1), "=r"(r2), "=r"(r3) : "r"(a));
}
__device__ __forceinline__ void mma_bf16(float* d, const uint32_t* a, const uint32_t* b) {
    asm volatile("mma.sync.aligned.m16n8k16.row.col.f32.bf16.bf16.f32 "
        "{%0,%1,%2,%3}, {%4,%5,%6,%7}, {%8,%9}, {%0,%1,%2,%3};"
        : "+f"(d[0]), "+f"(d[1]), "+f"(d[2]), "+f"(d[3])
        : "r"(a[0]), "r"(a[1]), "r"(a[2]), "r"(a[3]), "r"(b[0]), "r"(b[1]));
}
__device__ __forceinline__ void split2(float a, float b, uint32_t& hi, uint32_t& lo) {
    __nv_bfloat16 ha = __float2bfloat16(a), hb = __float2bfloat16(b);
    __nv_bfloat162 hp; hp.x = ha; hp.y = hb;
    __nv_bfloat162 lp;
    lp.x = __float2bfloat16(a - __bfloat162float(ha));
    lp.y = __float2bfloat16(b - __bfloat162float(hb));
    hi = *(uint32_t*)&hp; lo = *(uint32_t*)&lp;
}

// ===================== fp32 -> bf16 hi/lo split =============================
__global__ void __launch_bounds__(256) split_kernel(
    const float* __restrict__ x, __nv_bfloat16* __restrict__ hi,
    __nv_bfloat16* __restrict__ lo, int n4)
{
    int i = blockIdx.x * 256 + threadIdx.x;
    if (i >= n4) return;
    float4 v = ((const float4*)x)[i];
    uint32_t h0, l0, h1, l1;
    split2(v.x, v.y, h0, l0);
    split2(v.z, v.w, h1, l1);
    uint2 hv, lv;
    hv.x = h0; hv.y = h1; lv.x = l0; lv.y = l1;
    ((uint2*)hi)[i] = hv;
    ((uint2*)lo)[i] = lv;
}

// ============================================================================
// mma.sync GEMM: Y = X @ W^T + bias, split-bf16 (hh + hl + lh). (proven)
// ============================================================================
#define LDK   40
#define MAT_B (128 * LDK * 2)
#define BUF_B (4 * MAT_B)
#define PROJ_SMEM (2 * BUF_B)

template<int MODE>
__global__ void __launch_bounds__(256) mma_proj(
    const __nv_bfloat16* __restrict__ Xhi, const __nv_bfloat16* __restrict__ Xlo,
    const __nv_bfloat16* __restrict__ Whi, const __nv_bfloat16* __restrict__ Wlo,
    const float* __restrict__ bias, float* __restrict__ Yf,
    __nv_bfloat16* __restrict__ Yh, __nv_bfloat16* __restrict__ Yl)
{
    extern __shared__ char smem[];
    const int K = D_;
    int tid = threadIdx.x, wid = tid >> 5, lane = tid & 31;
    int bm = blockIdx.x * 128, bn = blockIdx.y * 128;
    int warp_m = (wid & 3) * 32, warp_n = (wid >> 2) * 64;

    uint32_t sbase = smem_u32(smem);

    int lrow = tid >> 1, lcol = (tid & 1) * 16;
    const __nv_bfloat16* gA_h = Xhi + (size_t)(bm + lrow) * K + lcol;
    const __nv_bfloat16* gA_l = Xlo + (size_t)(bm + lrow) * K + lcol;
    const __nv_bfloat16* gB_h = Whi + (size_t)(bn + lrow) * K + lcol;
    const __nv_bfloat16* gB_l = Wlo + (size_t)(bn + lrow) * K + lcol;
    uint32_t soff = (uint32_t)(lrow * LDK + lcol) * 2;

    auto issue_chunk = [&](int c, int buf) {
        uint32_t base = sbase + buf * BUF_B;
        int k0 = c * 32;
        #pragma unroll
        for (int h = 0; h < 2; h++) {
            uint32_t so = soff + h * 16;
            int go = k0 + h * 8;
            cp_async16(base + 0*MAT_B + so, gA_h + go);
            cp_async16(base + 1*MAT_B + so, gA_l + go);
            cp_async16(base + 2*MAT_B + so, gB_h + go);
            cp_async16(base + 3*MAT_B + so, gB_l + go);
        }
        cp_commit();
    };

    float acc[2][8][4];
    #pragma unroll
    for (int mf = 0; mf < 2; mf++)
        #pragma unroll
        for (int nf = 0; nf < 8; nf++)
            #pragma unroll
            for (int r = 0; r < 4; r++) acc[mf][nf][r] = 0.f;

    const int NCH = K / 32;
    issue_chunk(0, 0);
    int buf = 0;

    uint32_t a_off = (uint32_t)((warp_m + (lane & 15)) * LDK + (lane >> 4) * 8) * 2;
    uint32_t b_off = (uint32_t)((warp_n + ((lane >> 4) * 8) + (lane & 7)) * LDK
                                + (((lane >> 3) & 1) * 8)) * 2;

    for (int c = 0; c < NCH; c++) {
        if (c + 1 < NCH) { issue_chunk(c + 1, buf ^ 1); cp_wait<1>(); }
        else cp_wait<0>();
        __syncthreads();

        uint32_t base = sbase + buf * BUF_B;
        #pragma unroll
        for (int ks = 0; ks < 2; ks++) {
            uint32_t kso = (uint32_t)(ks * 16) * 2;
            uint32_t ah[2][4], al[2][4], bh[8][2], bl[8][2];
            #pragma unroll
            for (int mf = 0; mf < 2; mf++) {
                uint32_t ao = a_off + (uint32_t)(mf * 16 * LDK) * 2 + kso;
                ldm_x4(base + 0*MAT_B + ao, ah[mf][0], ah[mf][1], ah[mf][2], ah[mf][3]);
                ldm_x4(base + 1*MAT_B + ao, al[mf][0], al[mf][1], al[mf][2], al[mf][3]);
            }
            #pragma unroll
            for (int bg = 0; bg < 4; bg++) {
                uint32_t bo = b_off + (uint32_t)(bg * 16 * LDK) * 2 + kso;
                ldm_x4(base + 2*MAT_B + bo, bh[bg*2][0], bh[bg*2][1], bh[bg*2+1][0], bh[bg*2+1][1]);
                ldm_x4(base + 3*MAT_B + bo, bl[bg*2][0], bl[bg*2][1], bl[bg*2+1][0], bl[bg*2+1][1]);
            }
            #pragma unroll
            for (int mf = 0; mf < 2; mf++)
                #pragma unroll
                for (int nf = 0; nf < 8; nf++) {
                    mma_bf16(acc[mf][nf], ah[mf], bh[nf]);
                    mma_bf16(acc[mf][nf], ah[mf], bl[nf]);
                    mma_bf16(acc[mf][nf], al[mf], bh[nf]);
                }
        }
        __syncthreads();
        buf ^= 1;
    }

    int g = lane >> 2;
    #pragma unroll
    for (int nf = 0; nf < 8; nf++) {
        int n = bn + warp_n + nf * 8 + (lane & 3) * 2;
        float b0 = bias[n], b1 = bias[n + 1];
        #pragma unroll
        for (int mf = 0; mf < 2; mf++) {
            int m = bm + warp_m + mf * 16 + g;
            float2 o0, o1;
            o0.x = acc[mf][nf][0] + b0; o0.y = acc[mf][nf][1] + b1;
            o1.x = acc[mf][nf][2] + b0; o1.y = acc[mf][nf][3] + b1;
            if (MODE == 0) {
                int bb = m >> 10, s = m & 1023;
                int h = n >> 6, d = n & 63;
                size_t rb = (((size_t)bb * H_ + h) * S_);
                size_t i0 = (rb + s) * HD_ + d;
                size_t i1 = (rb + s + 8) * HD_ + d;
                uint32_t h0, l0, h1, l1;
                split2(o0.x, o0.y, h0, l0);
                split2(o1.x, o1.y, h1, l1);
                *(uint32_t*)&Yh[i0] = h0; *(uint32_t*)&Yl[i0] = l0;
                *(uint32_t*)&Yh[i1] = h1; *(uint32_t*)&Yl[i1] = l1;
            } else {
                *(float2*)&Yf[(size_t)m * D_ + n] = o0;
                *(float2*)&Yf[(size_t)(m + 8) * D_ + n] = o1;
            }
        }
    }
}

// ============================================================================
// Fused attention: scores + mask + softmax + attn write + P@V, two-pass.
// CTA = (q-tile of 128, bh). 8 warps x 16 q rows. k-chunks of 128.
// Outputs: attn probabilities (fp32) and ctx directly as bf16 hi/lo [M,D].
// ============================================================================
#define FLS 72
#define SQH 0
#define SQL 18432
#define SKH 36864
#define SKL 55296
#define SVH 73728
#define SVL 92160
#define SMSK 110592
#define FA_SMEM 114688

__global__ void __launch_bounds__(256) flash_attn(
    const __nv_bfloat16* __restrict__ qh, const __nv_bfloat16* __restrict__ ql,
    const __nv_bfloat16* __restrict__ kh, const __nv_bfloat16* __restrict__ kl,
    const __nv_bfloat16* __restrict__ vh, const __nv_bfloat16* __restrict__ vl,
    const int* __restrict__ mask, float* __restrict__ attn,
    __nv_bfloat16* __restrict__ ctx_hi, __nv_bfloat16* __restrict__ ctx_lo)
{
    extern __shared__ char smem[];
    int ibh = blockIdx.y;
    int b = ibh >> 4, h = ibh & 15;
    int bq = blockIdx.x * 128;
    int tid = threadIdx.x, wid = tid >> 5, lane = tid & 31;
    int wm = wid * 16;
    uint32_t sb = smem_u32(smem);

    const __nv_bfloat16* Qh = qh + ((size_t)ibh * S_ + bq) * HD_;
    const __nv_bfloat16* Ql = ql + ((size_t)ibh * S_ + bq) * HD_;
    const __nv_bfloat16* Kh = kh + (size_t)ibh * S_ * HD_;
    const __nv_bfloat16* Kl = kl + (size_t)ibh * S_ * HD_;
    const __nv_bfloat16* Vh = vh + (size_t)ibh * S_ * HD_;
    const __nv_bfloat16* Vl = vl + (size_t)ibh * S_ * HD_;
    const int* msk = (const int*)(smem + SMSK);

    // Q tile + mask
    #pragma unroll
    for (int t = 0; t < 4; t++) {
        int idx = tid + t * 256;
        int row = idx >> 3, pc = idx & 7;
        uint32_t so = (uint32_t)(row * FLS + pc * 8) * 2;
        size_t go = (size_t)row * HD_ + pc * 8;
        cp_async16(sb + SQH + so, Qh + go);
        cp_async16(sb + SQL + so, Ql + go);
    }
    cp_async16(sb + SMSK + tid * 16, mask + (size_t)b * S_ + tid * 4);
    cp_commit();

    uint32_t a_off = (uint32_t)((wm + (lane & 15)) * FLS + (lane >> 4) * 8) * 2;
    uint32_t b_off = (uint32_t)((((lane >> 4) * 8) + (lane & 7)) * FLS
                                + (((lane >> 3) & 1) * 8)) * 2;
    uint32_t v_off = (uint32_t)((lane & 15) * FLS + (lane >> 4) * 8) * 2;

    float mr0 = -1e30f, mr1 = -1e30f, lr0 = 0.f, lr1 = 0.f;

    cp_wait<0>();
    __syncthreads();

// ---- S tile compute macro: sf[16][4] = masked, scaled scores ----
#define COMPUTE_S(sf, ck)                                                        \
    {                                                                            \
        _Pragma("unroll")                                                        \
        for (int j = 0; j < 16; j++)                                             \
            _Pragma("unroll")                                                    \
            for (int r = 0; r < 4; r++) sf[j][r] = 0.f;                          \
        _Pragma("unroll")                                                        \
        for (int ks = 0; ks < 4; ks++) {                                         \
            uint32_t ahf[4], alf[4];                                             \
            uint32_t ao = a_off + (uint32_t)(ks * 32);                           \
            ldm_x4(sb + SQH + ao, ahf[0], ahf[1], ahf[2], ahf[3]);               \
            ldm_x4(sb + SQL + ao, alf[0], alf[1], alf[2], alf[3]);               \
            _Pragma("unroll")                                                    \
            for (int bg = 0; bg < 8; bg++) {                                     \
                uint32_t khf[2][2], klf[2][2];                                   \
                uint32_t bo = b_off + (uint32_t)(bg * 16 * FLS) * 2              \
                            + (uint32_t)(ks * 32);                               \
                ldm_x4(sb + SKH + bo, khf[0][0], khf[0][1], khf[1][0], khf[1][1]);\
                ldm_x4(sb + SKL + bo, klf[0][0], klf[0][1], klf[1][0], klf[1][1]);\
                mma_bf16(sf[bg*2],   ahf, khf[0]);                               \
                mma_bf16(sf[bg*2],   ahf, klf[0]);                               \
                mma_bf16(sf[bg*2],   alf, khf[0]);                               \
                mma_bf16(sf[bg*2+1], ahf, khf[1]);                               \
                mma_bf16(sf[bg*2+1], ahf, klf[1]);                               \
                mma_bf16(sf[bg*2+1], alf, khf[1]);                               \
            }                                                                    \
        }                                                                        \
        _Pragma("unroll")                                                        \
        for (int j = 0; j < 16; j++) {                                           \
            int n = (ck) + j * 8 + (lane & 3) * 2;                               \
            int mk0 = msk[n], mk1 = msk[n + 1];                                  \
            sf[j][0] = mk0 ? sf[j][0] * 0.125f : -1e10f;                         \
            sf[j][2] = mk0 ? sf[j][2] * 0.125f : -1e10f;                         \
            sf[j][1] = mk1 ? sf[j][1] * 0.125f : -1e10f;                         \
            sf[j][3] = mk1 ? sf[j][3] * 0.125f : -1e10f;                         \
        }                                                                        \
    }

    // ---------------- PASS 1: row max + sum ----------------
    for (int c = 0; c < 8; c++) {
        int ck = c * 128;
        #pragma unroll
        for (int t = 0; t < 4; t++) {
            int idx = tid + t * 256;
            int row = idx >> 3, pc = idx & 7;
            uint32_t so = (uint32_t)(row * FLS + pc * 8) * 2;
            size_t go = (size_t)(ck + row) * HD_ + pc * 8;
            cp_async16(sb + SKH + so, Kh + go);
            cp_async16(sb + SKL + so, Kl + go);
        }
        cp_commit();
        cp_wait<0>();
        __syncthreads();

        float sf[16][4];
        COMPUTE_S(sf, ck);

        float cm0 = -1e30f, cm1 = -1e30f;
        #pragma unroll
        for (int j = 0; j < 16; j++) {
            cm0 = fmaxf(cm0, fmaxf(sf[j][0], sf[j][1]));
            cm1 = fmaxf(cm1, fmaxf(sf[j][2], sf[j][3]));
        }
        cm0 = fmaxf(cm0, __shfl_xor_sync(0xffffffffu, cm0, 1));
        cm0 = fmaxf(cm0, __shfl_xor_sync(0xffffffffu, cm0, 2));
        cm1 = fmaxf(cm1, __shfl_xor_sync(0xffffffffu, cm1, 1));
        cm1 = fmaxf(cm1, __shfl_xor_sync(0xffffffffu, cm1, 2));
        float mn0 = fmaxf(mr0, cm0), mn1 = fmaxf(mr1, cm1);
        float s0 = 0.f, s1 = 0.f;
        #pragma unroll
        for (int j = 0; j < 16; j++) {
            s0 += __expf(sf[j][0] - mn0) + __expf(sf[j][1] - mn0);
            s1 += __expf(sf[j][2] - mn1) + __expf(sf[j][3] - mn1);
        }
        s0 += __shfl_xor_sync(0xffffffffu, s0, 1);
        s0 += __shfl_xor_sync(0xffffffffu, s0, 2);
        s1 += __shfl_xor_sync(0xffffffffu, s1, 1);
        s1 += __shfl_xor_sync(0xffffffffu, s1, 2);
        lr0 = lr0 * __expf(mr0 - mn0) + s0;
        lr1 = lr1 * __expf(mr1 - mn1) + s1;
        mr0 = mn0; mr1 = mn1;
        __syncthreads();
    }
    float inv0 = 1.f / lr0, inv1 = 1.f / lr1;

    // ---------------- PASS 2: p, attn write, O += P@V ----------------
    float oacc[8][4];
    #pragma unroll
    for (int nf = 0; nf < 8; nf++)
        #pragma unroll
        for (int r = 0; r < 4; r++) oacc[nf][r] = 0.f;

    int g = lane >> 2;
    int q0 = bq + wm + g;

    for (int c = 0; c < 8; c++) {
        int ck = c * 128;
        #pragma unroll
        for (int t = 0; t < 4; t++) {
            int idx = tid + t * 256;
            int row = idx >> 3, pc = idx & 7;
            uint32_t so = (uint32_t)(row * FLS + pc * 8) * 2;
            size_t go = (size_t)(ck + row) * HD_ + pc * 8;
            cp_async16(sb + SKH + so, Kh + go);
            cp_async16(sb + SKL + so, Kl + go);
            cp_async16(sb + SVH + so, Vh + go);
            cp_async16(sb + SVL + so, Vl + go);
        }
        cp_commit();
        cp_wait<0>();
        __syncthreads();

        float sf[16][4];
        COMPUTE_S(sf, ck);

        // probabilities + attn write
        #pragma unroll
        for (int j = 0; j < 16; j++) {
            float p0 = __expf(sf[j][0] - mr0) * inv0;
            float p1 = __expf(sf[j][1] - mr0) * inv0;
            float p2 = __expf(sf[j][2] - mr1) * inv1;
            float p3 = __expf(sf[j][3] - mr1) * inv1;
            sf[j][0] = p0; sf[j][1] = p1; sf[j][2] = p2; sf[j][3] = p3;
            int n = ck + j * 8 + (lane & 3) * 2;
            float2 w0; w0.x = p0; w0.y = p1;
            float2 w1; w1.x = p2; w1.y = p3;
            *(float2*)&attn[((size_t)ibh * S_ + q0) * S_ + n] = w0;
            *(float2*)&attn[((size_t)ibh * S_ + q0 + 8) * S_ + n] = w1;
        }

        // O += P @ V  (P frags packed in-register from sf)
        #pragma unroll
        for (int ks = 0; ks < 8; ks++) {
            uint32_t pah[4], pal[4];
            split2(sf[2*ks][0],   sf[2*ks][1],   pah[0], pal[0]);
            split2(sf[2*ks][2],   sf[2*ks][3],   pah[1], pal[1]);
            split2(sf[2*ks+1][0], sf[2*ks+1][1], pah[2], pal[2]);
            split2(sf[2*ks+1][2], sf[2*ks+1][3], pah[3], pal[3]);
            uint32_t bvh[8][2], bvl[8][2];
            #pragma unroll
            for (int ng = 0; ng < 4; ng++) {
                uint32_t vo = v_off + (uint32_t)(ks * 16 * FLS) * 2
                            + (uint32_t)(ng * 16) * 2;
                ldm_x4_t(sb + SVH + vo, bvh[ng*2][0], bvh[ng*2][1], bvh[ng*2+1][0], bvh[ng*2+1][1]);
                ldm_x4_t(sb + SVL + vo, bvl[ng*2][0], bvl[ng*2][1], bvl[ng*2+1][0], bvl[ng*2+1][1]);
            }
            #pragma unroll
            for (int nf = 0; nf < 8; nf++) {
                mma_bf16(oacc[nf], pah, bvh[nf]);
                mma_bf16(oacc[nf], pah, bvl[nf]);
                mma_bf16(oacc[nf], pal, bvh[nf]);
            }
        }
        __syncthreads();
    }

    // epilogue: ctx -> bf16 hi/lo merged [M, D]
    #pragma unroll
    for (int nf = 0; nf < 8; nf++) {
        int n = nf * 8 + (lane & 3) * 2;
        size_t i0 = ((size_t)b * S_ + q0) * D_ + h * HD_ + n;
        size_t i1 = ((size_t)b * S_ + q0 + 8) * D_ + h * HD_ + n;
        uint32_t h0, l0, h1, l1;
        split2(oacc[nf][0], oacc[nf][1], h0, l0);
        split2(oacc[nf][2], oacc[nf][3], h1, l1);
        *(uint32_t*)&ctx_hi[i0] = h0; *(uint32_t*)&ctx_lo[i0] = l0;
        *(uint32_t*)&ctx_hi[i1] = h1; *(uint32_t*)&ctx_lo[i1] = l1;
    }
#undef COMPUTE_S
}

// ============================================================================
extern "C" void kernel_launch(void* const* d_in, const int* in_sizes, int n_in,
                              void* d_out, int out_size)
{
    const float* query = (const float*)d_in[0];
    const float* key_  = (const float*)d_in[1];
    const float* value = (const float*)d_in[2];
    const int*   mask  = (const int*)d_in[3];
    const float* Wq = (const float*)d_in[4];  const float* bq = (const float*)d_in[5];
    const float* Wk = (const float*)d_in[6];  const float* bk = (const float*)d_in[7];
    const float* Wv = (const float*)d_in[8];  const float* bv = (const float*)d_in[9];
    const float* Wo = (const float*)d_in[10]; const float* bo = (const float*)d_in[11];
    float* out = (float*)d_out;

    float* pfb;
    __nv_bfloat16 *pxh, *pxl, *pwh, *pwl, *pqh, *pql, *pkh, *pkl, *pvh, *pvl;
    cudaGetSymbolAddress((void**)&pfb,  g_attn_fb);
    cudaGetSymbolAddress((void**)&pxh,  g_xhi);
    cudaGetSymbolAddress((void**)&pxl,  g_xlo);
    cudaGetSymbolAddress((void**)&pwh,  g_whi);
    cudaGetSymbolAddress((void**)&pwl,  g_wlo);
    cudaGetSymbolAddress((void**)&pqh,  g_qh);
    cudaGetSymbolAddress((void**)&pql,  g_ql);
    cudaGetSymbolAddress((void**)&pkh,  g_kh);
    cudaGetSymbolAddress((void**)&pkl,  g_kl);
    cudaGetSymbolAddress((void**)&pvh,  g_vh);
    cudaGetSymbolAddress((void**)&pvl,  g_vl);

    static bool attr_set = false;
    if (!attr_set) {
        cudaFuncSetAttribute(mma_proj<0>, cudaFuncAttributeMaxDynamicSharedMemorySize, PROJ_SMEM);
        cudaFuncSetAttribute(mma_proj<1>, cudaFuncAttributeMaxDynamicSharedMemorySize, PROJ_SMEM);
        cudaFuncSetAttribute(flash_attn, cudaFuncAttributeMaxDynamicSharedMemorySize, FA_SMEM);
        attr_set = true;
    }

    const size_t OUT_E = (size_t)M_ * D_;
    const size_t ATT_E = (size_t)B_ * H_ * S_ * S_;
    float* attn = ((size_t)out_size >= OUT_E + ATT_E) ? (out + OUT_E) : pfb;

    const int NX4 = M_ * D_ / 4;
    const int NW4 = D_ * D_ / 4;
    dim3 gx((NX4 + 255) / 256), gw((NW4 + 255) / 256);
    dim3 gproj(M_ / 128, D_ / 128);

    // Projections -> bf16 hi/lo head-split q/k/v
    split_kernel<<<gx, 256>>>(query, pxh, pxl, NX4);
    split_kernel<<<gw, 256>>>(Wq, pwh, pwl, NW4);
    mma_proj<0><<<gproj, 256, PROJ_SMEM>>>(pxh, pxl, pwh, pwl, bq, nullptr, pqh, pql);
    split_kernel<<<gx, 256>>>(key_, pxh, pxl, NX4);
    split_kernel<<<gw, 256>>>(Wk, pwh, pwl, NW4);
    mma_proj<0><<<gproj, 256, PROJ_SMEM>>>(pxh, pxl, pwh, pwl, bk, nullptr, pkh, pkl);
    split_kernel<<<gx, 256>>>(value, pxh, pxl, NX4);
    split_kernel<<<gw, 256>>>(Wv, pwh, pwl, NW4);
    mma_proj<0><<<gproj, 256, PROJ_SMEM>>>(pxh, pxl, pwh, pwl, bv, nullptr, pvh, pvl);

    // Fused attention: writes attn probs + ctx hi/lo (into pxh/pxl)
    dim3 gfa(S_ / 128, B_ * H_);
    flash_attn<<<gfa, 256, FA_SMEM>>>(pqh, pql, pkh, pkl, pvh, pvl, mask, attn, pxh, pxl);

    // Output projection (fp32 out), consumes pxh/pxl
    split_kernel<<<gw, 256>>>(Wo, pwh, pwl, NW4);
    mma_proj<1><<<gproj, 256, PROJ_SMEM>>>(pxh, pxl, pwh, pwl, bo, out, nullptr, nullptr);
}

// round 9
// speedup vs baseline: 1.0243x; 1.0243x over previous
#include <cuda_runtime.h>
#include <cuda_bf16.h>
#include <cstdint>

#define B_  4
#define S_  1024
#define D_  1024
#define H_  16
#define HD_ 64
#define M_  (B_*S_)

// ---------------- scratch (static __device__, no allocation) ----------------
__device__ float g_attn_fb[(size_t)B_*H_*S_*S_];
__device__ float g_linv[(size_t)B_*H_*S_];
__device__ __nv_bfloat16 g_xhi[(size_t)M_*D_];
__device__ __nv_bfloat16 g_xlo[(size_t)M_*D_];
__device__ __nv_bfloat16 g_whi[(size_t)D_*D_];
__device__ __nv_bfloat16 g_wlo[(size_t)D_*D_];
__device__ __nv_bfloat16 g_qh[(size_t)B_*H_*S_*HD_];
__device__ __nv_bfloat16 g_ql[(size_t)B_*H_*S_*HD_];
__device__ __nv_bfloat16 g_kh[(size_t)B_*H_*S_*HD_];
__device__ __nv_bfloat16 g_kl[(size_t)B_*H_*S_*HD_];
__device__ __nv_bfloat16 g_vh[(size_t)B_*H_*S_*HD_];
__device__ __nv_bfloat16 g_vl[(size_t)B_*H_*S_*HD_];

// ================= arch-neutral PTX helpers (sm_80-era only) ================
__device__ __forceinline__ uint32_t smem_u32(const void* p) {
    uint32_t a;
    asm("{ .reg .u64 t; cvta.to.shared.u64 t, %1; cvt.u32.u64 %0, t; }" : "=r"(a) : "l"(p));
    return a;
}
__device__ __forceinline__ void cp_async16(uint32_t sdst, const void* gsrc) {
    asm volatile("cp.async.cg.shared.global [%0], [%1], 16;" :: "r"(sdst), "l"(gsrc) : "memory");
}
__device__ __forceinline__ void cp_commit() {
    asm volatile("cp.async.commit_group;" ::: "memory");
}
template<int N>
__device__ __forceinline__ void cp_wait() {
    asm volatile("cp.async.wait_group %0;" :: "n"(N) : "memory");
}
__device__ __forceinline__ void ldm_x4(uint32_t a, uint32_t& r0, uint32_t& r1,
                                       uint32_t& r2, uint32_t& r3) {
    asm volatile("ldmatrix.sync.aligned.m8n8.x4.shared.b16 {%0,%1,%2,%3}, [%4];"
        : "=r"(r0), "=r"(r1), "=r"(r2), "=r"(r3) : "r"(a));
}
__device__ __forceinline__ void ldm_x4_t(uint32_t a, uint32_t& r0, uint32_t& r1,
                                         uint32_t& r2, uint32_t& r3) {
    asm volatile("ldmatrix.sync.aligned.m8n8.x4.trans.shared.b16 {%0,%1,%2,%3}, [%4];"
        : "=r"(r0), "=r"(r1), "=r"(r2), "=r"(r3) : "r"(a));
}
__device__ __forceinline__ void mma_bf16(float* d, const uint32_t* a, const uint32_t* b) {
    asm volatile("mma.sync.aligned.m16n8k16.row.col.f32.bf16.bf16.f32 "
        "{%0,%1,%2,%3}, {%4,%5,%6,%7}, {%8,%9}, {%0,%1,%2,%3};"
        : "+f"(d[0]), "+f"(d[1]), "+f"(d[2]), "+f"(d[3])
        : "r"(a[0]), "r"(a[1]), "r"(a[2]), "r"(a[3]), "r"(b[0]), "r"(b[1]));
}
__device__ __forceinline__ void split2(float a, float b, uint32_t& hi, uint32_t& lo) {
    __nv_bfloat16 ha = __float2bfloat16(a), hb = __float2bfloat16(b);
    __nv_bfloat162 hp; hp.x = ha; hp.y = hb;
    __nv_bfloat162 lp;
    lp.x = __float2bfloat16(a - __bfloat162float(ha));
    lp.y = __float2bfloat16(b - __bfloat162float(hb));
    hi = *(uint32_t*)&hp; lo = *(uint32_t*)&lp;
}

// ===================== fp32 -> bf16 hi/lo split (8 elems/thread) ============
__global__ void __launch_bounds__(256) split_kernel(
    const float* __restrict__ x, __nv_bfloat16* __restrict__ hi,
    __nv_bfloat16* __restrict__ lo, int n8)
{
    int i = blockIdx.x * 256 + threadIdx.x;
    if (i >= n8) return;
    float4 v0 = ((const float4*)x)[2*i];
    float4 v1 = ((const float4*)x)[2*i + 1];
    uint4 hv, lv;
    split2(v0.x, v0.y, hv.x, lv.x);
    split2(v0.z, v0.w, hv.y, lv.y);
    split2(v1.x, v1.y, hv.z, lv.z);
    split2(v1.z, v1.w, hv.w, lv.w);
    ((uint4*)hi)[i] = hv;
    ((uint4*)lo)[i] = lv;
}

// ============================================================================
// mma.sync GEMM: Y = X @ W^T + bias, split-bf16 (hh + hl + lh). (proven)
// ============================================================================
#define LDK   40
#define MAT_B (128 * LDK * 2)
#define BUF_B (4 * MAT_B)
#define PROJ_SMEM (2 * BUF_B)

template<int MODE>
__global__ void __launch_bounds__(256) mma_proj(
    const __nv_bfloat16* __restrict__ Xhi, const __nv_bfloat16* __restrict__ Xlo,
    const __nv_bfloat16* __restrict__ Whi, const __nv_bfloat16* __restrict__ Wlo,
    const float* __restrict__ bias, float* __restrict__ Yf,
    __nv_bfloat16* __restrict__ Yh, __nv_bfloat16* __restrict__ Yl)
{
    extern __shared__ char smem[];
    const int K = D_;
    int tid = threadIdx.x, wid = tid >> 5, lane = tid & 31;
    int bm = blockIdx.x * 128, bn = blockIdx.y * 128;
    int warp_m = (wid & 3) * 32, warp_n = (wid >> 2) * 64;

    uint32_t sbase = smem_u32(smem);

    int lrow = tid >> 1, lcol = (tid & 1) * 16;
    const __nv_bfloat16* gA_h = Xhi + (size_t)(bm + lrow) * K + lcol;
    const __nv_bfloat16* gA_l = Xlo + (size_t)(bm + lrow) * K + lcol;
    const __nv_bfloat16* gB_h = Whi + (size_t)(bn + lrow) * K + lcol;
    const __nv_bfloat16* gB_l = Wlo + (size_t)(bn + lrow) * K + lcol;
    uint32_t soff = (uint32_t)(lrow * LDK + lcol) * 2;

    auto issue_chunk = [&](int c, int buf) {
        uint32_t base = sbase + buf * BUF_B;
        int k0 = c * 32;
        #pragma unroll
        for (int h = 0; h < 2; h++) {
            uint32_t so = soff + h * 16;
            int go = k0 + h * 8;
            cp_async16(base + 0*MAT_B + so, gA_h + go);
            cp_async16(base + 1*MAT_B + so, gA_l + go);
            cp_async16(base + 2*MAT_B + so, gB_h + go);
            cp_async16(base + 3*MAT_B + so, gB_l + go);
        }
        cp_commit();
    };

    float acc[2][8][4];
    #pragma unroll
    for (int mf = 0; mf < 2; mf++)
        #pragma unroll
        for (int nf = 0; nf < 8; nf++)
            #pragma unroll
            for (int r = 0; r < 4; r++) acc[mf][nf][r] = 0.f;

    const int NCH = K / 32;
    issue_chunk(0, 0);
    int buf = 0;

    uint32_t a_off = (uint32_t)((warp_m + (lane & 15)) * LDK + (lane >> 4) * 8) * 2;
    uint32_t b_off = (uint32_t)((warp_n + ((lane >> 4) * 8) + (lane & 7)) * LDK
                                + (((lane >> 3) & 1) * 8)) * 2;

    for (int c = 0; c < NCH; c++) {
        if (c + 1 < NCH) { issue_chunk(c + 1, buf ^ 1); cp_wait<1>(); }
        else cp_wait<0>();
        __syncthreads();

        uint32_t base = sbase + buf * BUF_B;
        #pragma unroll
        for (int ks = 0; ks < 2; ks++) {
            uint32_t kso = (uint32_t)(ks * 16) * 2;
            uint32_t ah[2][4], al[2][4], bh[8][2], bl[8][2];
            #pragma unroll
            for (int mf = 0; mf < 2; mf++) {
                uint32_t ao = a_off + (uint32_t)(mf * 16 * LDK) * 2 + kso;
                ldm_x4(base + 0*MAT_B + ao, ah[mf][0], ah[mf][1], ah[mf][2], ah[mf][3]);
                ldm_x4(base + 1*MAT_B + ao, al[mf][0], al[mf][1], al[mf][2], al[mf][3]);
            }
            #pragma unroll
            for (int bg = 0; bg < 4; bg++) {
                uint32_t bo = b_off + (uint32_t)(bg * 16 * LDK) * 2 + kso;
                ldm_x4(base + 2*MAT_B + bo, bh[bg*2][0], bh[bg*2][1], bh[bg*2+1][0], bh[bg*2+1][1]);
                ldm_x4(base + 3*MAT_B + bo, bl[bg*2][0], bl[bg*2][1], bl[bg*2+1][0], bl[bg*2+1][1]);
            }
            #pragma unroll
            for (int mf = 0; mf < 2; mf++)
                #pragma unroll
                for (int nf = 0; nf < 8; nf++) {
                    mma_bf16(acc[mf][nf], ah[mf], bh[nf]);
                    mma_bf16(acc[mf][nf], ah[mf], bl[nf]);
                    mma_bf16(acc[mf][nf], al[mf], bh[nf]);
                }
        }
        __syncthreads();
        buf ^= 1;
    }

    int g = lane >> 2;
    #pragma unroll
    for (int nf = 0; nf < 8; nf++) {
        int n = bn + warp_n + nf * 8 + (lane & 3) * 2;
        float b0 = bias[n], b1 = bias[n + 1];
        #pragma unroll
        for (int mf = 0; mf < 2; mf++) {
            int m = bm + warp_m + mf * 16 + g;
            float2 o0, o1;
            o0.x = acc[mf][nf][0] + b0; o0.y = acc[mf][nf][1] + b1;
            o1.x = acc[mf][nf][2] + b0; o1.y = acc[mf][nf][3] + b1;
            if (MODE == 0) {
                int bb = m >> 10, s = m & 1023;
                int h = n >> 6, d = n & 63;
                size_t rb = (((size_t)bb * H_ + h) * S_);
                size_t i0 = (rb + s) * HD_ + d;
                size_t i1 = (rb + s + 8) * HD_ + d;
                uint32_t h0, l0, h1, l1;
                split2(o0.x, o0.y, h0, l0);
                split2(o1.x, o1.y, h1, l1);
                *(uint32_t*)&Yh[i0] = h0; *(uint32_t*)&Yl[i0] = l0;
                *(uint32_t*)&Yh[i1] = h1; *(uint32_t*)&Yl[i1] = l1;
            } else {
                *(float2*)&Yf[(size_t)m * D_ + n] = o0;
                *(float2*)&Yf[(size_t)(m + 8) * D_ + n] = o1;
            }
        }
    }
}

// ============================================================================
// Single-pass fused attention (m=0 softmax):
//   S = masked (Q@K^T)/8; e = exp(S) written UNNORMALIZED to attn;
//   l = row sum (registers); O = (sum e*V) / l -> ctx bf16 hi/lo; 1/l -> linv.
// CTA = (q-tile 128, bh), 8 warps x 16 rows, k-chunks 128, K/V double-buffered.
// ============================================================================
#define FLS 72
#define SQH 0
#define SQL 18432
#define KVB 36864
#define KVSZ 73728          // per buffer: KH,KL,VH,VL each 18432
#define SMSK (KVB + 2*KVSZ) // 184320
#define FA_SMEM (SMSK + 4096)

__global__ void __launch_bounds__(256) flash_attn(
    const __nv_bfloat16* __restrict__ qh, const __nv_bfloat16* __restrict__ ql,
    const __nv_bfloat16* __restrict__ kh, const __nv_bfloat16* __restrict__ kl,
    const __nv_bfloat16* __restrict__ vh, const __nv_bfloat16* __restrict__ vl,
    const int* __restrict__ mask, float* __restrict__ attn,
    __nv_bfloat16* __restrict__ ctx_hi, __nv_bfloat16* __restrict__ ctx_lo,
    float* __restrict__ linv)
{
    extern __shared__ char smem[];
    int ibh = blockIdx.y;
    int b = ibh >> 4, h = ibh & 15;
    int bq = blockIdx.x * 128;
    int tid = threadIdx.x, wid = tid >> 5, lane = tid & 31;
    int wm = wid * 16;
    uint32_t sb = smem_u32(smem);

    const __nv_bfloat16* Qh = qh + ((size_t)ibh * S_ + bq) * HD_;
    const __nv_bfloat16* Ql = ql + ((size_t)ibh * S_ + bq) * HD_;
    const __nv_bfloat16* Kh = kh + (size_t)ibh * S_ * HD_;
    const __nv_bfloat16* Kl = kl + (size_t)ibh * S_ * HD_;
    const __nv_bfloat16* Vh = vh + (size_t)ibh * S_ * HD_;
    const __nv_bfloat16* Vl = vl + (size_t)ibh * S_ * HD_;
    const int* msk = (const int*)(smem + SMSK);

    // group 0: Q tile + mask
    #pragma unroll
    for (int t = 0; t < 4; t++) {
        int idx = tid + t * 256;
        int row = idx >> 3, pc = idx & 7;
        uint32_t so = (uint32_t)(row * FLS + pc * 8) * 2;
        size_t go = (size_t)row * HD_ + pc * 8;
        cp_async16(sb + SQH + so, Qh + go);
        cp_async16(sb + SQL + so, Ql + go);
    }
    cp_async16(sb + SMSK + tid * 16, mask + (size_t)b * S_ + tid * 4);
    cp_commit();

    auto issue_kv = [&](int c, int buf) {
        uint32_t base = sb + KVB + buf * KVSZ;
        int k0 = c * 128;
        #pragma unroll
        for (int t = 0; t < 4; t++) {
            int idx = tid + t * 256;
            int row = idx >> 3, pc = idx & 7;
            uint32_t so = (uint32_t)(row * FLS + pc * 8) * 2;
            size_t go = (size_t)(k0 + row) * HD_ + pc * 8;
            cp_async16(base + 0     + so, Kh + go);
            cp_async16(base + 18432 + so, Kl + go);
            cp_async16(base + 36864 + so, Vh + go);
            cp_async16(base + 55296 + so, Vl + go);
        }
        cp_commit();
    };

    uint32_t a_off = (uint32_t)((wm + (lane & 15)) * FLS + (lane >> 4) * 8) * 2;
    uint32_t b_off = (uint32_t)((((lane >> 4) * 8) + (lane & 7)) * FLS
                                + (((lane >> 3) & 1) * 8)) * 2;
    uint32_t v_off = (uint32_t)((lane & 15) * FLS + (lane >> 4) * 8) * 2;

    issue_kv(0, 0);

    float lsum0 = 0.f, lsum1 = 0.f;
    float oacc[8][4];
    #pragma unroll
    for (int nf = 0; nf < 8; nf++)
        #pragma unroll
        for (int r = 0; r < 4; r++) oacc[nf][r] = 0.f;

    // Q fragments hoisted (need Q smem ready: wait all, then first-chunk
    // overlap is sacrificed only at c=0 which also needs KV0 anyway)
    cp_wait<1>();       // Q+mask group complete (KV0 may be in flight)
    __syncthreads();
    uint32_t qfh[4][4], qfl[4][4];
    #pragma unroll
    for (int ks = 0; ks < 4; ks++) {
        uint32_t ao = a_off + (uint32_t)(ks * 32);
        ldm_x4(sb + SQH + ao, qfh[ks][0], qfh[ks][1], qfh[ks][2], qfh[ks][3]);
        ldm_x4(sb + SQL + ao, qfl[ks][0], qfl[ks][1], qfl[ks][2], qfl[ks][3]);
    }

    int g = lane >> 2;
    int q0 = bq + wm + g;

    for (int c = 0; c < 8; c++) {
        if (c < 7) { issue_kv(c + 1, (c + 1) & 1); cp_wait<1>(); }
        else cp_wait<0>();
        __syncthreads();

        uint32_t kvb = sb + KVB + (c & 1) * KVSZ;
        int ck = c * 128;

        // ---- S = Q@K^T (3-term) ----
        float sf[16][4];
        #pragma unroll
        for (int j = 0; j < 16; j++)
            #pragma unroll
            for (int r = 0; r < 4; r++) sf[j][r] = 0.f;
        #pragma unroll
        for (int ks = 0; ks < 4; ks++) {
            #pragma unroll
            for (int bg = 0; bg < 8; bg++) {
                uint32_t khf[2][2], klf[2][2];
                uint32_t bo = b_off + (uint32_t)(bg * 16 * FLS) * 2 + (uint32_t)(ks * 32);
                ldm_x4(kvb + 0     + bo, khf[0][0], khf[0][1], khf[1][0], khf[1][1]);
                ldm_x4(kvb + 18432 + bo, klf[0][0], klf[0][1], klf[1][0], klf[1][1]);
                mma_bf16(sf[bg*2],   qfh[ks], khf[0]);
                mma_bf16(sf[bg*2],   qfh[ks], klf[0]);
                mma_bf16(sf[bg*2],   qfl[ks], khf[0]);
                mma_bf16(sf[bg*2+1], qfh[ks], khf[1]);
                mma_bf16(sf[bg*2+1], qfh[ks], klf[1]);
                mma_bf16(sf[bg*2+1], qfl[ks], khf[1]);
            }
        }

        // ---- mask/scale, exp (m=0), l accumulate, unnormalized attn write ----
        #pragma unroll
        for (int j = 0; j < 16; j++) {
            int n = ck + j * 8 + (lane & 3) * 2;
            int mk0 = msk[n], mk1 = msk[n + 1];
            float e0 = mk0 ? __expf(sf[j][0] * 0.125f) : 0.f;
            float e1 = mk1 ? __expf(sf[j][1] * 0.125f) : 0.f;
            float e2 = mk0 ? __expf(sf[j][2] * 0.125f) : 0.f;
            float e3 = mk1 ? __expf(sf[j][3] * 0.125f) : 0.f;
            lsum0 += e0 + e1; lsum1 += e2 + e3;
            sf[j][0] = e0; sf[j][1] = e1; sf[j][2] = e2; sf[j][3] = e3;
            float2 w0; w0.x = e0; w0.y = e1;
            float2 w1; w1.x = e2; w1.y = e3;
            *(float2*)&attn[((size_t)ibh * S_ + q0) * S_ + n] = w0;
            *(float2*)&attn[((size_t)ibh * S_ + q0 + 8) * S_ + n] = w1;
        }

        // ---- O += E @ V ----
        #pragma unroll
        for (int ks = 0; ks < 8; ks++) {
            uint32_t pah[4], pal[4];
            split2(sf[2*ks][0],   sf[2*ks][1],   pah[0], pal[0]);
            split2(sf[2*ks][2],   sf[2*ks][3],   pah[1], pal[1]);
            split2(sf[2*ks+1][0], sf[2*ks+1][1], pah[2], pal[2]);
            split2(sf[2*ks+1][2], sf[2*ks+1][3], pah[3], pal[3]);
            uint32_t bvh[8][2], bvl[8][2];
            #pragma unroll
            for (int ng = 0; ng < 4; ng++) {
                uint32_t vo = v_off + (uint32_t)(ks * 16 * FLS) * 2 + (uint32_t)(ng * 16) * 2;
                ldm_x4_t(kvb + 36864 + vo, bvh[ng*2][0], bvh[ng*2][1], bvh[ng*2+1][0], bvh[ng*2+1][1]);
                ldm_x4_t(kvb + 55296 + vo, bvl[ng*2][0], bvl[ng*2][1], bvl[ng*2+1][0], bvl[ng*2+1][1]);
            }
            #pragma unroll
            for (int nf = 0; nf < 8; nf++) {
                mma_bf16(oacc[nf], pah, bvh[nf]);
                mma_bf16(oacc[nf], pah, bvl[nf]);
                mma_bf16(oacc[nf], pal, bvh[nf]);
            }
        }
        __syncthreads();
    }

    // ---- finalize: l reduce, linv store, O/l -> ctx bf16 hi/lo ----
    lsum0 += __shfl_xor_sync(0xffffffffu, lsum0, 1);
    lsum0 += __shfl_xor_sync(0xffffffffu, lsum0, 2);
    lsum1 += __shfl_xor_sync(0xffffffffu, lsum1, 1);
    lsum1 += __shfl_xor_sync(0xffffffffu, lsum1, 2);
    float inv0 = 1.f / lsum0, inv1 = 1.f / lsum1;
    if ((lane & 3) == 0) {
        linv[(size_t)ibh * S_ + q0] = inv0;
        linv[(size_t)ibh * S_ + q0 + 8] = inv1;
    }
    #pragma unroll
    for (int nf = 0; nf < 8; nf++) {
        int n = nf * 8 + (lane & 3) * 2;
        size_t i0 = ((size_t)b * S_ + q0) * D_ + h * HD_ + n;
        size_t i1 = ((size_t)b * S_ + q0 + 8) * D_ + h * HD_ + n;
        uint32_t h0, l0, h1, l1;
        split2(oacc[nf][0] * inv0, oacc[nf][1] * inv0, h0, l0);
        split2(oacc[nf][2] * inv1, oacc[nf][3] * inv1, h1, l1);
        *(uint32_t*)&ctx_hi[i0] = h0; *(uint32_t*)&ctx_lo[i0] = l0;
        *(uint32_t*)&ctx_hi[i1] = h1; *(uint32_t*)&ctx_lo[i1] = l1;
    }
}

// ============================================================================
// attn normalization: row *= 1/l.  One block per row.
// ============================================================================
__global__ void __launch_bounds__(256) rescale_kernel(
    float* __restrict__ attn, const float* __restrict__ linv)
{
    size_t row = blockIdx.x;
    float inv = __ldg(&linv[row]);
    float4* p = reinterpret_cast<float4*>(attn + row * S_);
    float4 v = p[threadIdx.x];
    v.x *= inv; v.y *= inv; v.z *= inv; v.w *= inv;
    p[threadIdx.x] = v;
}

// ============================================================================
extern "C" void kernel_launch(void* const* d_in, const int* in_sizes, int n_in,
                              void* d_out, int out_size)
{
    const float* query = (const float*)d_in[0];
    const float* key_  = (const float*)d_in[1];
    const float* value = (const float*)d_in[2];
    const int*   mask  = (const int*)d_in[3];
    const float* Wq = (const float*)d_in[4];  const float* bq = (const float*)d_in[5];
    const float* Wk = (const float*)d_in[6];  const float* bk = (const float*)d_in[7];
    const float* Wv = (const float*)d_in[8];  const float* bv = (const float*)d_in[9];
    const float* Wo = (const float*)d_in[10]; const float* bo = (const float*)d_in[11];
    float* out = (float*)d_out;

    float *pfb, *plinv;
    __nv_bfloat16 *pxh, *pxl, *pwh, *pwl, *pqh, *pql, *pkh, *pkl, *pvh, *pvl;
    cudaGetSymbolAddress((void**)&pfb,   g_attn_fb);
    cudaGetSymbolAddress((void**)&plinv, g_linv);
    cudaGetSymbolAddress((void**)&pxh,  g_xhi);
    cudaGetSymbolAddress((void**)&pxl,  g_xlo);
    cudaGetSymbolAddress((void**)&pwh,  g_whi);
    cudaGetSymbolAddress((void**)&pwl,  g_wlo);
    cudaGetSymbolAddress((void**)&pqh,  g_qh);
    cudaGetSymbolAddress((void**)&pql,  g_ql);
    cudaGetSymbolAddress((void**)&pkh,  g_kh);
    cudaGetSymbolAddress((void**)&pkl,  g_kl);
    cudaGetSymbolAddress((void**)&pvh,  g_vh);
    cudaGetSymbolAddress((void**)&pvl,  g_vl);

    static bool attr_set = false;
    if (!attr_set) {
        cudaFuncSetAttribute(mma_proj<0>, cudaFuncAttributeMaxDynamicSharedMemorySize, PROJ_SMEM);
        cudaFuncSetAttribute(mma_proj<1>, cudaFuncAttributeMaxDynamicSharedMemorySize, PROJ_SMEM);
        cudaFuncSetAttribute(flash_attn, cudaFuncAttributeMaxDynamicSharedMemorySize, FA_SMEM);
        attr_set = true;
    }

    const size_t OUT_E = (size_t)M_ * D_;
    const size_t ATT_E = (size_t)B_ * H_ * S_ * S_;
    float* attn = ((size_t)out_size >= OUT_E + ATT_E) ? (out + OUT_E) : pfb;

    const int NX8 = M_ * D_ / 8;
    const int NW8 = D_ * D_ / 8;
    dim3 gx(NX8 / 256), gw(NW8 / 256);
    dim3 gproj(M_ / 128, D_ / 128);

    // Projections -> bf16 hi/lo head-split q/k/v
    split_kernel<<<gx, 256>>>(query, pxh, pxl, NX8);
    split_kernel<<<gw, 256>>>(Wq, pwh, pwl, NW8);
    mma_proj<0><<<gproj, 256, PROJ_SMEM>>>(pxh, pxl, pwh, pwl, bq, nullptr, pqh, pql);
    split_kernel<<<gx, 256>>>(key_, pxh, pxl, NX8);
    split_kernel<<<gw, 256>>>(Wk, pwh, pwl, NW8);
    mma_proj<0><<<gproj, 256, PROJ_SMEM>>>(pxh, pxl, pwh, pwl, bk, nullptr, pkh, pkl);
    split_kernel<<<gx, 256>>>(value, pxh, pxl, NX8);
    split_kernel<<<gw, 256>>>(Wv, pwh, pwl, NW8);
    mma_proj<0><<<gproj, 256, PROJ_SMEM>>>(pxh, pxl, pwh, pwl, bv, nullptr, pvh, pvl);

    // Single-pass fused attention: unnormalized e -> attn, ctx hi/lo, 1/l
    dim3 gfa(S_ / 128, B_ * H_);
    flash_attn<<<gfa, 256, FA_SMEM>>>(pqh, pql, pkh, pkl, pvh, pvl, mask, attn,
                                      pxh, pxl, plinv);

    // Normalize attn rows
    rescale_kernel<<<B_ * H_ * S_, 256>>>(attn, plinv);

    // Output projection (fp32 out), consumes ctx hi/lo in pxh/pxl
    split_kernel<<<gw, 256>>>(Wo, pwh, pwl, NW8);
    mma_proj<1><<<gproj, 256, PROJ_SMEM>>>(pxh, pxl, pwh, pwl, bo, out, nullptr, nullptr);
}

// round 10
// speedup vs baseline: 1.4307x; 1.3968x over previous
#include <cuda_runtime.h>
#include <cuda_fp16.h>
#include <cstdint>

#define B_  4
#define S_  1024
#define D_  1024
#define H_  16
#define HD_ 64
#define M_  (B_*S_)

// ---------------- scratch (static __device__, no allocation) ----------------
__device__ float g_attn_fb[(size_t)B_*H_*S_*S_];
__device__ float g_linv[(size_t)B_*H_*S_];
__device__ __half g_xhi[(size_t)M_*D_];
__device__ __half g_xlo[(size_t)M_*D_];
__device__ __half g_whi[(size_t)D_*D_];
__device__ __half g_qh[(size_t)B_*H_*S_*HD_];
__device__ __half g_ql[(size_t)B_*H_*S_*HD_];
__device__ __half g_kh[(size_t)B_*H_*S_*HD_];
__device__ __half g_kl[(size_t)B_*H_*S_*HD_];
__device__ __half g_vh[(size_t)B_*H_*S_*HD_];
__device__ __half g_vl[(size_t)B_*H_*S_*HD_];

// ================= arch-neutral PTX helpers (sm_80-era only) ================
__device__ __forceinline__ uint32_t smem_u32(const void* p) {
    uint32_t a;
    asm("{ .reg .u64 t; cvta.to.shared.u64 t, %1; cvt.u32.u64 %0, t; }" : "=r"(a) : "l"(p));
    return a;
}
__device__ __forceinline__ void cp_async16(uint32_t sdst, const void* gsrc) {
    asm volatile("cp.async.cg.shared.global [%0], [%1], 16;" :: "r"(sdst), "l"(gsrc) : "memory");
}
__device__ __forceinline__ void cp_commit() {
    asm volatile("cp.async.commit_group;" ::: "memory");
}
template<int N>
__device__ __forceinline__ void cp_wait() {
    asm volatile("cp.async.wait_group %0;" :: "n"(N) : "memory");
}
__device__ __forceinline__ void ldm_x4(uint32_t a, uint32_t& r0, uint32_t& r1,
                                       uint32_t& r2, uint32_t& r3) {
    asm volatile("ldmatrix.sync.aligned.m8n8.x4.shared.b16 {%0,%1,%2,%3}, [%4];"
        : "=r"(r0), "=r"(r1), "=r"(r2), "=r"(r3) : "r"(a));
}
__device__ __forceinline__ void ldm_x4_t(uint32_t a, uint32_t& r0, uint32_t& r1,
                                         uint32_t& r2, uint32_t& r3) {
    asm volatile("ldmatrix.sync.aligned.m8n8.x4.trans.shared.b16 {%0,%1,%2,%3}, [%4];"
        : "=r"(r0), "=r"(r1), "=r"(r2), "=r"(r3) : "r"(a));
}
__device__ __forceinline__ void mma_f16(float* d, const uint32_t* a, const uint32_t* b) {
    asm volatile("mma.sync.aligned.m16n8k16.row.col.f32.f16.f16.f32 "
        "{%0,%1,%2,%3}, {%4,%5,%6,%7}, {%8,%9}, {%0,%1,%2,%3};"
        : "+f"(d[0]), "+f"(d[1]), "+f"(d[2]), "+f"(d[3])
        : "r"(a[0]), "r"(a[1]), "r"(a[2]), "r"(a[3]), "r"(b[0]), "r"(b[1]));
}
__device__ __forceinline__ uint32_t cvt2h(float a, float b) {
    __half2 p; p.x = __float2half_rn(a); p.y = __float2half_rn(b);
    return *(uint32_t*)&p;
}
__device__ __forceinline__ void split2h(float a, float b, uint32_t& hi, uint32_t& lo) {
    __half ha = __float2half_rn(a), hb = __float2half_rn(b);
    __half2 hp; hp.x = ha; hp.y = hb;
    __half2 lp;
    lp.x = __float2half_rn(a - __half2float(ha));
    lp.y = __float2half_rn(b - __half2float(hb));
    hi = *(uint32_t*)&hp; lo = *(uint32_t*)&lp;
}

// ===================== fp32 -> fp16 hi/lo split (8 elems/thread) ============
__global__ void __launch_bounds__(256) split_hl(
    const float* __restrict__ x, __half* __restrict__ hi,
    __half* __restrict__ lo, int n8)
{
    int i = blockIdx.x * 256 + threadIdx.x;
    if (i >= n8) return;
    float4 v0 = ((const float4*)x)[2*i];
    float4 v1 = ((const float4*)x)[2*i + 1];
    uint4 hv, lv;
    split2h(v0.x, v0.y, hv.x, lv.x);
    split2h(v0.z, v0.w, hv.y, lv.y);
    split2h(v1.x, v1.y, hv.z, lv.z);
    split2h(v1.z, v1.w, hv.w, lv.w);
    ((uint4*)hi)[i] = hv;
    ((uint4*)lo)[i] = lv;
}
// hi-only convert (for weights, 1-term side)
__global__ void __launch_bounds__(256) conv_h(
    const float* __restrict__ x, __half* __restrict__ hi, int n8)
{
    int i = blockIdx.x * 256 + threadIdx.x;
    if (i >= n8) return;
    float4 v0 = ((const float4*)x)[2*i];
    float4 v1 = ((const float4*)x)[2*i + 1];
    uint4 hv;
    hv.x = cvt2h(v0.x, v0.y); hv.y = cvt2h(v0.z, v0.w);
    hv.z = cvt2h(v1.x, v1.y); hv.w = cvt2h(v1.z, v1.w);
    ((uint4*)hi)[i] = hv;
}

// ============================================================================
// mma.sync GEMM 2-term fp16: Y = (Xh+Xl) @ Wh^T + bias.
// CTA 128x128, kChunk=32, 8 warps (32x64), double-buffered cp.async.
// MODE 0: head-split fp16 hi/lo outputs. MODE 1: fp32 [M,N].
// ============================================================================
#define LDK   40
#define MAT_B (128 * LDK * 2)
#define BUF_B (3 * MAT_B)             // Ah, Al, Bh
#define PROJ_SMEM (2 * BUF_B)         // 61440

template<int MODE>
__global__ void __launch_bounds__(256) mma_proj(
    const __half* __restrict__ Xhi, const __half* __restrict__ Xlo,
    const __half* __restrict__ Whi,
    const float* __restrict__ bias, float* __restrict__ Yf,
    __half* __restrict__ Yh, __half* __restrict__ Yl)
{
    extern __shared__ char smem[];
    const int K = D_;
    int tid = threadIdx.x, wid = tid >> 5, lane = tid & 31;
    int bm = blockIdx.x * 128, bn = blockIdx.y * 128;
    int warp_m = (wid & 3) * 32, warp_n = (wid >> 2) * 64;

    uint32_t sbase = smem_u32(smem);

    int lrow = tid >> 1, lcol = (tid & 1) * 16;
    const __half* gA_h = Xhi + (size_t)(bm + lrow) * K + lcol;
    const __half* gA_l = Xlo + (size_t)(bm + lrow) * K + lcol;
    const __half* gB_h = Whi + (size_t)(bn + lrow) * K + lcol;
    uint32_t soff = (uint32_t)(lrow * LDK + lcol) * 2;

    auto issue_chunk = [&](int c, int buf) {
        uint32_t base = sbase + buf * BUF_B;
        int k0 = c * 32;
        #pragma unroll
        for (int h = 0; h < 2; h++) {
            uint32_t so = soff + h * 16;
            int go = k0 + h * 8;
            cp_async16(base + 0*MAT_B + so, gA_h + go);
            cp_async16(base + 1*MAT_B + so, gA_l + go);
            cp_async16(base + 2*MAT_B + so, gB_h + go);
        }
        cp_commit();
    };

    float acc[2][8][4];
    #pragma unroll
    for (int mf = 0; mf < 2; mf++)
        #pragma unroll
        for (int nf = 0; nf < 8; nf++)
            #pragma unroll
            for (int r = 0; r < 4; r++) acc[mf][nf][r] = 0.f;

    const int NCH = K / 32;
    issue_chunk(0, 0);
    int buf = 0;

    uint32_t a_off = (uint32_t)((warp_m + (lane & 15)) * LDK + (lane >> 4) * 8) * 2;
    uint32_t b_off = (uint32_t)((warp_n + ((lane >> 4) * 8) + (lane & 7)) * LDK
                                + (((lane >> 3) & 1) * 8)) * 2;

    for (int c = 0; c < NCH; c++) {
        if (c + 1 < NCH) { issue_chunk(c + 1, buf ^ 1); cp_wait<1>(); }
        else cp_wait<0>();
        __syncthreads();

        uint32_t base = sbase + buf * BUF_B;
        #pragma unroll
        for (int ks = 0; ks < 2; ks++) {
            uint32_t kso = (uint32_t)(ks * 16) * 2;
            uint32_t ah[2][4], al[2][4], bh[8][2];
            #pragma unroll
            for (int mf = 0; mf < 2; mf++) {
                uint32_t ao = a_off + (uint32_t)(mf * 16 * LDK) * 2 + kso;
                ldm_x4(base + 0*MAT_B + ao, ah[mf][0], ah[mf][1], ah[mf][2], ah[mf][3]);
                ldm_x4(base + 1*MAT_B + ao, al[mf][0], al[mf][1], al[mf][2], al[mf][3]);
            }
            #pragma unroll
            for (int bg = 0; bg < 4; bg++) {
                uint32_t bo = b_off + (uint32_t)(bg * 16 * LDK) * 2 + kso;
                ldm_x4(base + 2*MAT_B + bo, bh[bg*2][0], bh[bg*2][1], bh[bg*2+1][0], bh[bg*2+1][1]);
            }
            #pragma unroll
            for (int mf = 0; mf < 2; mf++)
                #pragma unroll
                for (int nf = 0; nf < 8; nf++) {
                    mma_f16(acc[mf][nf], ah[mf], bh[nf]);
                    mma_f16(acc[mf][nf], al[mf], bh[nf]);
                }
        }
        __syncthreads();
        buf ^= 1;
    }

    int g = lane >> 2;
    #pragma unroll
    for (int nf = 0; nf < 8; nf++) {
        int n = bn + warp_n + nf * 8 + (lane & 3) * 2;
        float b0 = bias[n], b1 = bias[n + 1];
        #pragma unroll
        for (int mf = 0; mf < 2; mf++) {
            int m = bm + warp_m + mf * 16 + g;
            float2 o0, o1;
            o0.x = acc[mf][nf][0] + b0; o0.y = acc[mf][nf][1] + b1;
            o1.x = acc[mf][nf][2] + b0; o1.y = acc[mf][nf][3] + b1;
            if (MODE == 0) {
                int bb = m >> 10, s = m & 1023;
                int h = n >> 6, d = n & 63;
                size_t rb = (((size_t)bb * H_ + h) * S_);
                size_t i0 = (rb + s) * HD_ + d;
                size_t i1 = (rb + s + 8) * HD_ + d;
                uint32_t h0, l0, h1, l1;
                split2h(o0.x, o0.y, h0, l0);
                split2h(o1.x, o1.y, h1, l1);
                *(uint32_t*)&Yh[i0] = h0; *(uint32_t*)&Yl[i0] = l0;
                *(uint32_t*)&Yh[i1] = h1; *(uint32_t*)&Yl[i1] = l1;
            } else {
                *(float2*)&Yf[(size_t)m * D_ + n] = o0;
                *(float2*)&Yf[(size_t)(m + 8) * D_ + n] = o1;
            }
        }
    }
}

// ============================================================================
// Single-pass fused attention (m=0 softmax), fp16 2-term:
//   S = (Qh+Ql)@Kh^T /8 masked; e=exp(S) unnormalized -> attn; l in regs;
//   O = sum eh*(Vh+Vl); ctx = O/l -> fp16 hi/lo; 1/l -> linv.
// ============================================================================
#define FLS 72
#define SQH 0
#define SQL 18432
#define KVB 36864
#define KVSZ 55296            // per buffer: KH, VH, VL each 18432
#define SMSK (KVB + 2*KVSZ)   // 147456
#define FA_SMEM (SMSK + 4096) // 151552

__global__ void __launch_bounds__(256) flash_attn(
    const __half* __restrict__ qh, const __half* __restrict__ ql,
    const __half* __restrict__ kh,
    const __half* __restrict__ vh, const __half* __restrict__ vl,
    const int* __restrict__ mask, float* __restrict__ attn,
    __half* __restrict__ ctx_hi, __half* __restrict__ ctx_lo,
    float* __restrict__ linv)
{
    extern __shared__ char smem[];
    int ibh = blockIdx.y;
    int b = ibh >> 4, h = ibh & 15;
    int bq = blockIdx.x * 128;
    int tid = threadIdx.x, wid = tid >> 5, lane = tid & 31;
    int wm = wid * 16;
    uint32_t sb = smem_u32(smem);

    const __half* Qh = qh + ((size_t)ibh * S_ + bq) * HD_;
    const __half* Ql = ql + ((size_t)ibh * S_ + bq) * HD_;
    const __half* Kh = kh + (size_t)ibh * S_ * HD_;
    const __half* Vh = vh + (size_t)ibh * S_ * HD_;
    const __half* Vl = vl + (size_t)ibh * S_ * HD_;
    const int* msk = (const int*)(smem + SMSK);

    // group 0: Q tile + mask
    #pragma unroll
    for (int t = 0; t < 4; t++) {
        int idx = tid + t * 256;
        int row = idx >> 3, pc = idx & 7;
        uint32_t so = (uint32_t)(row * FLS + pc * 8) * 2;
        size_t go = (size_t)row * HD_ + pc * 8;
        cp_async16(sb + SQH + so, Qh + go);
        cp_async16(sb + SQL + so, Ql + go);
    }
    cp_async16(sb + SMSK + tid * 16, mask + (size_t)b * S_ + tid * 4);
    cp_commit();

    auto issue_kv = [&](int c, int buf) {
        uint32_t base = sb + KVB + buf * KVSZ;
        int k0 = c * 128;
        #pragma unroll
        for (int t = 0; t < 4; t++) {
            int idx = tid + t * 256;
            int row = idx >> 3, pc = idx & 7;
            uint32_t so = (uint32_t)(row * FLS + pc * 8) * 2;
            size_t go = (size_t)(k0 + row) * HD_ + pc * 8;
            cp_async16(base + 0     + so, Kh + go);
            cp_async16(base + 18432 + so, Vh + go);
            cp_async16(base + 36864 + so, Vl + go);
        }
        cp_commit();
    };

    uint32_t a_off = (uint32_t)((wm + (lane & 15)) * FLS + (lane >> 4) * 8) * 2;
    uint32_t b_off = (uint32_t)((((lane >> 4) * 8) + (lane & 7)) * FLS
                                + (((lane >> 3) & 1) * 8)) * 2;
    uint32_t v_off = (uint32_t)((lane & 15) * FLS + (lane >> 4) * 8) * 2;

    issue_kv(0, 0);

    float lsum0 = 0.f, lsum1 = 0.f;
    float oacc[8][4];
    #pragma unroll
    for (int nf = 0; nf < 8; nf++)
        #pragma unroll
        for (int r = 0; r < 4; r++) oacc[nf][r] = 0.f;

    cp_wait<1>();       // Q+mask complete (KV0 may still be in flight)
    __syncthreads();
    uint32_t qfh[4][4], qfl[4][4];
    #pragma unroll
    for (int ks = 0; ks < 4; ks++) {
        uint32_t ao = a_off + (uint32_t)(ks * 32);
        ldm_x4(sb + SQH + ao, qfh[ks][0], qfh[ks][1], qfh[ks][2], qfh[ks][3]);
        ldm_x4(sb + SQL + ao, qfl[ks][0], qfl[ks][1], qfl[ks][2], qfl[ks][3]);
    }

    int g = lane >> 2;
    int q0 = bq + wm + g;

    for (int c = 0; c < 8; c++) {
        if (c < 7) { issue_kv(c + 1, (c + 1) & 1); cp_wait<1>(); }
        else cp_wait<0>();
        __syncthreads();

        uint32_t kvb = sb + KVB + (c & 1) * KVSZ;
        int ck = c * 128;

        // ---- S = (Qh+Ql)@Kh^T ----
        float sf[16][4];
        #pragma unroll
        for (int j = 0; j < 16; j++)
            #pragma unroll
            for (int r = 0; r < 4; r++) sf[j][r] = 0.f;
        #pragma unroll
        for (int ks = 0; ks < 4; ks++) {
            #pragma unroll
            for (int bg = 0; bg < 8; bg++) {
                uint32_t khf[2][2];
                uint32_t bo = b_off + (uint32_t)(bg * 16 * FLS) * 2 + (uint32_t)(ks * 32);
                ldm_x4(kvb + bo, khf[0][0], khf[0][1], khf[1][0], khf[1][1]);
                mma_f16(sf[bg*2],   qfh[ks], khf[0]);
                mma_f16(sf[bg*2],   qfl[ks], khf[0]);
                mma_f16(sf[bg*2+1], qfh[ks], khf[1]);
                mma_f16(sf[bg*2+1], qfl[ks], khf[1]);
            }
        }

        // ---- mask/scale, exp (m=0), l accumulate, unnormalized attn write ----
        #pragma unroll
        for (int j = 0; j < 16; j++) {
            int n = ck + j * 8 + (lane & 3) * 2;
            int mk0 = msk[n], mk1 = msk[n + 1];
            float e0 = mk0 ? __expf(sf[j][0] * 0.125f) : 0.f;
            float e1 = mk1 ? __expf(sf[j][1] * 0.125f) : 0.f;
            float e2 = mk0 ? __expf(sf[j][2] * 0.125f) : 0.f;
            float e3 = mk1 ? __expf(sf[j][3] * 0.125f) : 0.f;
            lsum0 += e0 + e1; lsum1 += e2 + e3;
            sf[j][0] = e0; sf[j][1] = e1; sf[j][2] = e2; sf[j][3] = e3;
            float2 w0; w0.x = e0; w0.y = e1;
            float2 w1; w1.x = e2; w1.y = e3;
            *(float2*)&attn[((size_t)ibh * S_ + q0) * S_ + n] = w0;
            *(float2*)&attn[((size_t)ibh * S_ + q0 + 8) * S_ + n] = w1;
        }

        // ---- O += Eh @ (Vh + Vl) ----
        #pragma unroll
        for (int ks = 0; ks < 8; ks++) {
            uint32_t pah[4];
            pah[0] = cvt2h(sf[2*ks][0],   sf[2*ks][1]);
            pah[1] = cvt2h(sf[2*ks][2],   sf[2*ks][3]);
            pah[2] = cvt2h(sf[2*ks+1][0], sf[2*ks+1][1]);
            pah[3] = cvt2h(sf[2*ks+1][2], sf[2*ks+1][3]);
            uint32_t bvh[8][2], bvl[8][2];
            #pragma unroll
            for (int ng = 0; ng < 4; ng++) {
                uint32_t vo = v_off + (uint32_t)(ks * 16 * FLS) * 2 + (uint32_t)(ng * 16) * 2;
                ldm_x4_t(kvb + 18432 + vo, bvh[ng*2][0], bvh[ng*2][1], bvh[ng*2+1][0], bvh[ng*2+1][1]);
                ldm_x4_t(kvb + 36864 + vo, bvl[ng*2][0], bvl[ng*2][1], bvl[ng*2+1][0], bvl[ng*2+1][1]);
            }
            #pragma unroll
            for (int nf = 0; nf < 8; nf++) {
                mma_f16(oacc[nf], pah, bvh[nf]);
                mma_f16(oacc[nf], pah, bvl[nf]);
            }
        }
        __syncthreads();
    }

    // ---- finalize ----
    lsum0 += __shfl_xor_sync(0xffffffffu, lsum0, 1);
    lsum0 += __shfl_xor_sync(0xffffffffu, lsum0, 2);
    lsum1 += __shfl_xor_sync(0xffffffffu, lsum1, 1);
    lsum1 += __shfl_xor_sync(0xffffffffu, lsum1, 2);
    float inv0 = 1.f / lsum0, inv1 = 1.f / lsum1;
    if ((lane & 3) == 0) {
        linv[(size_t)ibh * S_ + q0] = inv0;
        linv[(size_t)ibh * S_ + q0 + 8] = inv1;
    }
    #pragma unroll
    for (int nf = 0; nf < 8; nf++) {
        int n = nf * 8 + (lane & 3) * 2;
        size_t i0 = ((size_t)b * S_ + q0) * D_ + h * HD_ + n;
        size_t i1 = ((size_t)b * S_ + q0 + 8) * D_ + h * HD_ + n;
        uint32_t h0, l0, h1, l1;
        split2h(oacc[nf][0] * inv0, oacc[nf][1] * inv0, h0, l0);
        split2h(oacc[nf][2] * inv1, oacc[nf][3] * inv1, h1, l1);
        *(uint32_t*)&ctx_hi[i0] = h0; *(uint32_t*)&ctx_lo[i0] = l0;
        *(uint32_t*)&ctx_hi[i1] = h1; *(uint32_t*)&ctx_lo[i1] = l1;
    }
}

// ============================================================================
// attn normalization: row *= 1/l.
// ============================================================================
__global__ void __launch_bounds__(256) rescale_kernel(
    float* __restrict__ attn, const float* __restrict__ linv)
{
    size_t row = blockIdx.x;
    float inv = __ldg(&linv[row]);
    float4* p = reinterpret_cast<float4*>(attn + row * S_);
    float4 v = p[threadIdx.x];
    v.x *= inv; v.y *= inv; v.z *= inv; v.w *= inv;
    p[threadIdx.x] = v;
}

// ============================================================================
extern "C" void kernel_launch(void* const* d_in, const int* in_sizes, int n_in,
                              void* d_out, int out_size)
{
    const float* query = (const float*)d_in[0];
    const float* key_  = (const float*)d_in[1];
    const float* value = (const float*)d_in[2];
    const int*   mask  = (const int*)d_in[3];
    const float* Wq = (const float*)d_in[4];  const float* bq = (const float*)d_in[5];
    const float* Wk = (const float*)d_in[6];  const float* bk = (const float*)d_in[7];
    const float* Wv = (const float*)d_in[8];  const float* bv = (const float*)d_in[9];
    const float* Wo = (const float*)d_in[10]; const float* bo = (const float*)d_in[11];
    float* out = (float*)d_out;

    float *pfb, *plinv;
    __half *pxh, *pxl, *pwh, *pqh, *pql, *pkh, *pkl, *pvh, *pvl;
    cudaGetSymbolAddress((void**)&pfb,   g_attn_fb);
    cudaGetSymbolAddress((void**)&plinv, g_linv);
    cudaGetSymbolAddress((void**)&pxh,  g_xhi);
    cudaGetSymbolAddress((void**)&pxl,  g_xlo);
    cudaGetSymbolAddress((void**)&pwh,  g_whi);
    cudaGetSymbolAddress((void**)&pqh,  g_qh);
    cudaGetSymbolAddress((void**)&pql,  g_ql);
    cudaGetSymbolAddress((void**)&pkh,  g_kh);
    cudaGetSymbolAddress((void**)&pkl,  g_kl);
    cudaGetSymbolAddress((void**)&pvh,  g_vh);
    cudaGetSymbolAddress((void**)&pvl,  g_vl);

    static bool attr_set = false;
    if (!attr_set) {
        cudaFuncSetAttribute(mma_proj<0>, cudaFuncAttributeMaxDynamicSharedMemorySize, PROJ_SMEM);
        cudaFuncSetAttribute(mma_proj<1>, cudaFuncAttributeMaxDynamicSharedMemorySize, PROJ_SMEM);
        cudaFuncSetAttribute(flash_attn, cudaFuncAttributeMaxDynamicSharedMemorySize, FA_SMEM);
        attr_set = true;
    }

    const size_t OUT_E = (size_t)M_ * D_;
    const size_t ATT_E = (size_t)B_ * H_ * S_ * S_;
    float* attn = ((size_t)out_size >= OUT_E + ATT_E) ? (out + OUT_E) : pfb;

    const int NX8 = M_ * D_ / 8;
    const int NW8 = D_ * D_ / 8;
    dim3 gx(NX8 / 256), gw(NW8 / 256);
    dim3 gproj(M_ / 128, D_ / 128);

    // Q projection
    split_hl<<<gx, 256>>>(query, pxh, pxl, NX8);
    conv_h<<<gw, 256>>>(Wq, pwh, NW8);
    mma_proj<0><<<gproj, 256, PROJ_SMEM>>>(pxh, pxl, pwh, bq, nullptr, pqh, pql);
    // K projection (only hi consumed by flash, lo written harmlessly to g_kl)
    split_hl<<<gx, 256>>>(key_, pxh, pxl, NX8);
    conv_h<<<gw, 256>>>(Wk, pwh, NW8);
    mma_proj<0><<<gproj, 256, PROJ_SMEM>>>(pxh, pxl, pwh, bk, nullptr, pkh, pkl);
    // V projection
    split_hl<<<gx, 256>>>(value, pxh, pxl, NX8);
    conv_h<<<gw, 256>>>(Wv, pwh, NW8);
    mma_proj<0><<<gproj, 256, PROJ_SMEM>>>(pxh, pxl, pwh, bv, nullptr, pvh, pvl);

    // Fused attention
    dim3 gfa(S_ / 128, B_ * H_);
    flash_attn<<<gfa, 256, FA_SMEM>>>(pqh, pql, pkh, pvh, pvl, mask, attn,
                                      pxh, pxl, plinv);

    // Normalize attn rows
    rescale_kernel<<<B_ * H_ * S_, 256>>>(attn, plinv);

    // Output projection
    conv_h<<<gw, 256>>>(Wo, pwh, NW8);
    mma_proj<1><<<gproj, 256, PROJ_SMEM>>>(pxh, pxl, pwh, bo, out, nullptr, nullptr);
}

// round 11
// speedup vs baseline: 1.4834x; 1.0368x over previous
#include <cuda_runtime.h>
#include <cuda_fp16.h>
#include <cstdint>

#define B_  4
#define S_  1024
#define D_  1024
#define H_  16
#define HD_ 64
#define M_  (B_*S_)
#define QKV_E ((size_t)B_*H_*S_*HD_)   // 4M elements per tensor

// ---------------- scratch (static __device__, no allocation) ----------------
__device__ float g_attn_fb[(size_t)B_*H_*S_*S_];
__device__ __half g_xh3[3*(size_t)M_*D_];     // split inputs (hi); [0] reused for ctx_hi
__device__ __half g_xl3[3*(size_t)M_*D_];     // split inputs (lo); [0] reused for ctx_lo
__device__ __half g_wh4[4*(size_t)D_*D_];     // Wq,Wk,Wv,Wo hi
__device__ __half g_qkvh[3*QKV_E];            // q,k,v hi (head-split)
__device__ __half g_qkvl[3*QKV_E];            // q,k,v lo

// ================= arch-neutral PTX helpers (sm_80-era only) ================
__device__ __forceinline__ uint32_t smem_u32(const void* p) {
    uint32_t a;
    asm("{ .reg .u64 t; cvta.to.shared.u64 t, %1; cvt.u32.u64 %0, t; }" : "=r"(a) : "l"(p));
    return a;
}
__device__ __forceinline__ void cp_async16(uint32_t sdst, const void* gsrc) {
    asm volatile("cp.async.cg.shared.global [%0], [%1], 16;" :: "r"(sdst), "l"(gsrc) : "memory");
}
__device__ __forceinline__ void cp_commit() {
    asm volatile("cp.async.commit_group;" ::: "memory");
}
template<int N>
__device__ __forceinline__ void cp_wait() {
    asm volatile("cp.async.wait_group %0;" :: "n"(N) : "memory");
}
__device__ __forceinline__ void ldm_x4(uint32_t a, uint32_t& r0, uint32_t& r1,
                                       uint32_t& r2, uint32_t& r3) {
    asm volatile("ldmatrix.sync.aligned.m8n8.x4.shared.b16 {%0,%1,%2,%3}, [%4];"
        : "=r"(r0), "=r"(r1), "=r"(r2), "=r"(r3) : "r"(a));
}
__device__ __forceinline__ void ldm_x4_t(uint32_t a, uint32_t& r0, uint32_t& r1,
                                         uint32_t& r2, uint32_t& r3) {
    asm volatile("ldmatrix.sync.aligned.m8n8.x4.trans.shared.b16 {%0,%1,%2,%3}, [%4];"
        : "=r"(r0), "=r"(r1), "=r"(r2), "=r"(r3) : "r"(a));
}
__device__ __forceinline__ void mma_f16(float* d, const uint32_t* a, const uint32_t* b) {
    asm volatile("mma.sync.aligned.m16n8k16.row.col.f32.f16.f16.f32 "
        "{%0,%1,%2,%3}, {%4,%5,%6,%7}, {%8,%9}, {%0,%1,%2,%3};"
        : "+f"(d[0]), "+f"(d[1]), "+f"(d[2]), "+f"(d[3])
        : "r"(a[0]), "r"(a[1]), "r"(a[2]), "r"(a[3]), "r"(b[0]), "r"(b[1]));
}
__device__ __forceinline__ uint32_t cvt2h(float a, float b) {
    __half2 p; p.x = __float2half_rn(a); p.y = __float2half_rn(b);
    return *(uint32_t*)&p;
}
__device__ __forceinline__ void split2h(float a, float b, uint32_t& hi, uint32_t& lo) {
    __half ha = __float2half_rn(a), hb = __float2half_rn(b);
    __half2 hp; hp.x = ha; hp.y = hb;
    __half2 lp;
    lp.x = __float2half_rn(a - __half2float(ha));
    lp.y = __float2half_rn(b - __half2float(hb));
    hi = *(uint32_t*)&hp; lo = *(uint32_t*)&lp;
}

// ======= merged fp32 -> fp16 hi/lo split for query/key/value (z grid) =======
__global__ void __launch_bounds__(256) split3_kernel(
    const float* __restrict__ q, const float* __restrict__ k,
    const float* __restrict__ v, int n8)
{
    int z = blockIdx.y;
    const float* x = (z == 0) ? q : (z == 1) ? k : v;
    __half* hi = g_xh3 + (size_t)z * M_ * D_;
    __half* lo = g_xl3 + (size_t)z * M_ * D_;
    int i = blockIdx.x * 256 + threadIdx.x;
    if (i >= n8) return;
    float4 v0 = ((const float4*)x)[2*i];
    float4 v1 = ((const float4*)x)[2*i + 1];
    uint4 hv, lv;
    split2h(v0.x, v0.y, hv.x, lv.x);
    split2h(v0.z, v0.w, hv.y, lv.y);
    split2h(v1.x, v1.y, hv.z, lv.z);
    split2h(v1.z, v1.w, hv.w, lv.w);
    ((uint4*)hi)[i] = hv;
    ((uint4*)lo)[i] = lv;
}

// ============ merged weight fp32 -> fp16 convert (4 weights, z grid) ========
__global__ void __launch_bounds__(256) convw_kernel(
    const float* __restrict__ wq, const float* __restrict__ wk,
    const float* __restrict__ wv, const float* __restrict__ wo, int n8)
{
    int z = blockIdx.y;
    const float* x = (z == 0) ? wq : (z == 1) ? wk : (z == 2) ? wv : wo;
    __half* hi = g_wh4 + (size_t)z * D_ * D_;
    int i = blockIdx.x * 256 + threadIdx.x;
    if (i >= n8) return;
    float4 v0 = ((const float4*)x)[2*i];
    float4 v1 = ((const float4*)x)[2*i + 1];
    uint4 hv;
    hv.x = cvt2h(v0.x, v0.y); hv.y = cvt2h(v0.z, v0.w);
    hv.z = cvt2h(v1.x, v1.y); hv.w = cvt2h(v1.z, v1.w);
    ((uint4*)hi)[i] = hv;
}

// ============================================================================
// GEMM core (2-term fp16): shared between qkv_proj (MODE 0, z-merged) and
// out_proj (MODE 1).  CTA 128x128, kChunk=32, 8 warps, double-buffered.
// ============================================================================
#define LDK   40
#define MAT_B (128 * LDK * 2)
#define BUF_B (3 * MAT_B)
#define PROJ_SMEM (2 * BUF_B)

template<int MODE>
__device__ __forceinline__ void proj_body(
    const __half* __restrict__ Xhi, const __half* __restrict__ Xlo,
    const __half* __restrict__ Whi, const float* __restrict__ bias,
    float* __restrict__ Yf, __half* __restrict__ Yh, __half* __restrict__ Yl,
    char* smem)
{
    const int K = D_;
    int tid = threadIdx.x, wid = tid >> 5, lane = tid & 31;
    int bm = blockIdx.x * 128, bn = blockIdx.y * 128;
    int warp_m = (wid & 3) * 32, warp_n = (wid >> 2) * 64;
    uint32_t sbase = smem_u32(smem);

    int lrow = tid >> 1, lcol = (tid & 1) * 16;
    const __half* gA_h = Xhi + (size_t)(bm + lrow) * K + lcol;
    const __half* gA_l = Xlo + (size_t)(bm + lrow) * K + lcol;
    const __half* gB_h = Whi + (size_t)(bn + lrow) * K + lcol;
    uint32_t soff = (uint32_t)(lrow * LDK + lcol) * 2;

    auto issue_chunk = [&](int c, int buf) {
        uint32_t base = sbase + buf * BUF_B;
        int k0 = c * 32;
        #pragma unroll
        for (int h = 0; h < 2; h++) {
            uint32_t so = soff + h * 16;
            int go = k0 + h * 8;
            cp_async16(base + 0*MAT_B + so, gA_h + go);
            cp_async16(base + 1*MAT_B + so, gA_l + go);
            cp_async16(base + 2*MAT_B + so, gB_h + go);
        }
        cp_commit();
    };

    float acc[2][8][4];
    #pragma unroll
    for (int mf = 0; mf < 2; mf++)
        #pragma unroll
        for (int nf = 0; nf < 8; nf++)
            #pragma unroll
            for (int r = 0; r < 4; r++) acc[mf][nf][r] = 0.f;

    const int NCH = K / 32;
    issue_chunk(0, 0);
    int buf = 0;

    uint32_t a_off = (uint32_t)((warp_m + (lane & 15)) * LDK + (lane >> 4) * 8) * 2;
    uint32_t b_off = (uint32_t)((warp_n + ((lane >> 4) * 8) + (lane & 7)) * LDK
                                + (((lane >> 3) & 1) * 8)) * 2;

    for (int c = 0; c < NCH; c++) {
        if (c + 1 < NCH) { issue_chunk(c + 1, buf ^ 1); cp_wait<1>(); }
        else cp_wait<0>();
        __syncthreads();

        uint32_t base = sbase + buf * BUF_B;
        #pragma unroll
        for (int ks = 0; ks < 2; ks++) {
            uint32_t kso = (uint32_t)(ks * 16) * 2;
            uint32_t ah[2][4], al[2][4], bh[8][2];
            #pragma unroll
            for (int mf = 0; mf < 2; mf++) {
                uint32_t ao = a_off + (uint32_t)(mf * 16 * LDK) * 2 + kso;
                ldm_x4(base + 0*MAT_B + ao, ah[mf][0], ah[mf][1], ah[mf][2], ah[mf][3]);
                ldm_x4(base + 1*MAT_B + ao, al[mf][0], al[mf][1], al[mf][2], al[mf][3]);
            }
            #pragma unroll
            for (int bg = 0; bg < 4; bg++) {
                uint32_t bo = b_off + (uint32_t)(bg * 16 * LDK) * 2 + kso;
                ldm_x4(base + 2*MAT_B + bo, bh[bg*2][0], bh[bg*2][1], bh[bg*2+1][0], bh[bg*2+1][1]);
            }
            #pragma unroll
            for (int mf = 0; mf < 2; mf++)
                #pragma unroll
                for (int nf = 0; nf < 8; nf++) {
                    mma_f16(acc[mf][nf], ah[mf], bh[nf]);
                    mma_f16(acc[mf][nf], al[mf], bh[nf]);
                }
        }
        __syncthreads();
        buf ^= 1;
    }

    int g = lane >> 2;
    #pragma unroll
    for (int nf = 0; nf < 8; nf++) {
        int n = bn + warp_n + nf * 8 + (lane & 3) * 2;
        float b0 = bias[n], b1 = bias[n + 1];
        #pragma unroll
        for (int mf = 0; mf < 2; mf++) {
            int m = bm + warp_m + mf * 16 + g;
            float2 o0, o1;
            o0.x = acc[mf][nf][0] + b0; o0.y = acc[mf][nf][1] + b1;
            o1.x = acc[mf][nf][2] + b0; o1.y = acc[mf][nf][3] + b1;
            if (MODE == 0) {
                int bb = m >> 10, s = m & 1023;
                int h = n >> 6, d = n & 63;
                size_t rb = (((size_t)bb * H_ + h) * S_);
                size_t i0 = (rb + s) * HD_ + d;
                size_t i1 = (rb + s + 8) * HD_ + d;
                uint32_t h0, l0, h1, l1;
                split2h(o0.x, o0.y, h0, l0);
                split2h(o1.x, o1.y, h1, l1);
                *(uint32_t*)&Yh[i0] = h0; *(uint32_t*)&Yl[i0] = l0;
                *(uint32_t*)&Yh[i1] = h1; *(uint32_t*)&Yl[i1] = l1;
            } else {
                *(float2*)&Yf[(size_t)m * D_ + n] = o0;
                *(float2*)&Yf[(size_t)(m + 8) * D_ + n] = o1;
            }
        }
    }
}

// Merged Q/K/V projection: z in {0,1,2}
__global__ void __launch_bounds__(256) qkv_proj(
    const float* __restrict__ bq, const float* __restrict__ bk,
    const float* __restrict__ bv)
{
    extern __shared__ char smem[];
    int z = blockIdx.z;
    const float* bias = (z == 0) ? bq : (z == 1) ? bk : bv;
    proj_body<0>(g_xh3 + (size_t)z * M_ * D_, g_xl3 + (size_t)z * M_ * D_,
                 g_wh4 + (size_t)z * D_ * D_, bias, nullptr,
                 g_qkvh + (size_t)z * QKV_E, g_qkvl + (size_t)z * QKV_E, smem);
}

// Output projection: ctx hi/lo live in g_xh3[0]/g_xl3[0]
__global__ void __launch_bounds__(256) out_proj(
    const float* __restrict__ bo, float* __restrict__ out)
{
    extern __shared__ char smem[];
    proj_body<1>(g_xh3, g_xl3, g_wh4 + 3 * (size_t)D_ * D_, bo, out,
                 nullptr, nullptr, smem);
}

// ============================================================================
// Single-pass fused attention + in-kernel tail rescale.
//   e = exp(masked (Qh+Ql)@Kh^T / 8) written unnormalized; l in regs;
//   ctx = (sum e*(Vh+Vl))/l -> fp16 hi/lo; tail: own attn tile *= 1/l (L2-warm)
// ============================================================================
#define FLS 72
#define SQH 0
#define SQL 18432
#define KVB 36864
#define KVSZ 55296
#define SMSK (KVB + 2*KVSZ)       // 147456
#define SINV (SMSK + 4096)        // 151552
#define FA_SMEM (SINV + 512)      // 152064

__global__ void __launch_bounds__(256) flash_attn(
    const int* __restrict__ mask, float* __restrict__ attn,
    __half* __restrict__ ctx_hi, __half* __restrict__ ctx_lo)
{
    extern __shared__ char smem[];
    int ibh = blockIdx.y;
    int b = ibh >> 4, h = ibh & 15;
    int bq = blockIdx.x * 128;
    int tid = threadIdx.x, wid = tid >> 5, lane = tid & 31;
    int wm = wid * 16;
    uint32_t sb = smem_u32(smem);

    const __half* Qh = g_qkvh + ((size_t)ibh * S_ + bq) * HD_;
    const __half* Ql = g_qkvl + ((size_t)ibh * S_ + bq) * HD_;
    const __half* Kh = g_qkvh + QKV_E + (size_t)ibh * S_ * HD_;
    const __half* Vh = g_qkvh + 2 * QKV_E + (size_t)ibh * S_ * HD_;
    const __half* Vl = g_qkvl + 2 * QKV_E + (size_t)ibh * S_ * HD_;
    const int* msk = (const int*)(smem + SMSK);
    float* sinv = (float*)(smem + SINV);

    #pragma unroll
    for (int t = 0; t < 4; t++) {
        int idx = tid + t * 256;
        int row = idx >> 3, pc = idx & 7;
        uint32_t so = (uint32_t)(row * FLS + pc * 8) * 2;
        size_t go = (size_t)row * HD_ + pc * 8;
        cp_async16(sb + SQH + so, Qh + go);
        cp_async16(sb + SQL + so, Ql + go);
    }
    cp_async16(sb + SMSK + tid * 16, mask + (size_t)b * S_ + tid * 4);
    cp_commit();

    auto issue_kv = [&](int c, int buf) {
        uint32_t base = sb + KVB + buf * KVSZ;
        int k0 = c * 128;
        #pragma unroll
        for (int t = 0; t < 4; t++) {
            int idx = tid + t * 256;
            int row = idx >> 3, pc = idx & 7;
            uint32_t so = (uint32_t)(row * FLS + pc * 8) * 2;
            size_t go = (size_t)(k0 + row) * HD_ + pc * 8;
            cp_async16(base + 0     + so, Kh + go);
            cp_async16(base + 18432 + so, Vh + go);
            cp_async16(base + 36864 + so, Vl + go);
        }
        cp_commit();
    };

    uint32_t a_off = (uint32_t)((wm + (lane & 15)) * FLS + (lane >> 4) * 8) * 2;
    uint32_t b_off = (uint32_t)((((lane >> 4) * 8) + (lane & 7)) * FLS
                                + (((lane >> 3) & 1) * 8)) * 2;
    uint32_t v_off = (uint32_t)((lane & 15) * FLS + (lane >> 4) * 8) * 2;

    issue_kv(0, 0);

    float lsum0 = 0.f, lsum1 = 0.f;
    float oacc[8][4];
    #pragma unroll
    for (int nf = 0; nf < 8; nf++)
        #pragma unroll
        for (int r = 0; r < 4; r++) oacc[nf][r] = 0.f;

    cp_wait<1>();
    __syncthreads();
    uint32_t qfh[4][4], qfl[4][4];
    #pragma unroll
    for (int ks = 0; ks < 4; ks++) {
        uint32_t ao = a_off + (uint32_t)(ks * 32);
        ldm_x4(sb + SQH + ao, qfh[ks][0], qfh[ks][1], qfh[ks][2], qfh[ks][3]);
        ldm_x4(sb + SQL + ao, qfl[ks][0], qfl[ks][1], qfl[ks][2], qfl[ks][3]);
    }

    int g = lane >> 2;
    int q0 = bq + wm + g;

    for (int c = 0; c < 8; c++) {
        if (c < 7) { issue_kv(c + 1, (c + 1) & 1); cp_wait<1>(); }
        else cp_wait<0>();
        __syncthreads();

        uint32_t kvb = sb + KVB + (c & 1) * KVSZ;
        int ck = c * 128;

        float sf[16][4];
        #pragma unroll
        for (int j = 0; j < 16; j++)
            #pragma unroll
            for (int r = 0; r < 4; r++) sf[j][r] = 0.f;
        #pragma unroll
        for (int ks = 0; ks < 4; ks++) {
            #pragma unroll
            for (int bg = 0; bg < 8; bg++) {
                uint32_t khf[2][2];
                uint32_t bo = b_off + (uint32_t)(bg * 16 * FLS) * 2 + (uint32_t)(ks * 32);
                ldm_x4(kvb + bo, khf[0][0], khf[0][1], khf[1][0], khf[1][1]);
                mma_f16(sf[bg*2],   qfh[ks], khf[0]);
                mma_f16(sf[bg*2],   qfl[ks], khf[0]);
                mma_f16(sf[bg*2+1], qfh[ks], khf[1]);
                mma_f16(sf[bg*2+1], qfl[ks], khf[1]);
            }
        }

        #pragma unroll
        for (int j = 0; j < 16; j++) {
            int n = ck + j * 8 + (lane & 3) * 2;
            int mk0 = msk[n], mk1 = msk[n + 1];
            float e0 = mk0 ? __expf(sf[j][0] * 0.125f) : 0.f;
            float e1 = mk1 ? __expf(sf[j][1] * 0.125f) : 0.f;
            float e2 = mk0 ? __expf(sf[j][2] * 0.125f) : 0.f;
            float e3 = mk1 ? __expf(sf[j][3] * 0.125f) : 0.f;
            lsum0 += e0 + e1; lsum1 += e2 + e3;
            sf[j][0] = e0; sf[j][1] = e1; sf[j][2] = e2; sf[j][3] = e3;
            float2 w0; w0.x = e0; w0.y = e1;
            float2 w1; w1.x = e2; w1.y = e3;
            *(float2*)&attn[((size_t)ibh * S_ + q0) * S_ + n] = w0;
            *(float2*)&attn[((size_t)ibh * S_ + q0 + 8) * S_ + n] = w1;
        }

        #pragma unroll
        for (int ks = 0; ks < 8; ks++) {
            uint32_t pah[4];
            pah[0] = cvt2h(sf[2*ks][0],   sf[2*ks][1]);
            pah[1] = cvt2h(sf[2*ks][2],   sf[2*ks][3]);
            pah[2] = cvt2h(sf[2*ks+1][0], sf[2*ks+1][1]);
            pah[3] = cvt2h(sf[2*ks+1][2], sf[2*ks+1][3]);
            uint32_t bvh[8][2], bvl[8][2];
            #pragma unroll
            for (int ng = 0; ng < 4; ng++) {
                uint32_t vo = v_off + (uint32_t)(ks * 16 * FLS) * 2 + (uint32_t)(ng * 16) * 2;
                ldm_x4_t(kvb + 18432 + vo, bvh[ng*2][0], bvh[ng*2][1], bvh[ng*2+1][0], bvh[ng*2+1][1]);
                ldm_x4_t(kvb + 36864 + vo, bvl[ng*2][0], bvl[ng*2][1], bvl[ng*2+1][0], bvl[ng*2+1][1]);
            }
            #pragma unroll
            for (int nf = 0; nf < 8; nf++) {
                mma_f16(oacc[nf], pah, bvh[nf]);
                mma_f16(oacc[nf], pah, bvl[nf]);
            }
        }
        __syncthreads();
    }

    // ---- finalize: reduce l, publish 1/l to smem, write ctx ----
    lsum0 += __shfl_xor_sync(0xffffffffu, lsum0, 1);
    lsum0 += __shfl_xor_sync(0xffffffffu, lsum0, 2);
    lsum1 += __shfl_xor_sync(0xffffffffu, lsum1, 1);
    lsum1 += __shfl_xor_sync(0xffffffffu, lsum1, 2);
    float inv0 = 1.f / lsum0, inv1 = 1.f / lsum1;
    if ((lane & 3) == 0) {
        sinv[wm + g] = inv0;
        sinv[wm + g + 8] = inv1;
    }
    #pragma unroll
    for (int nf = 0; nf < 8; nf++) {
        int n = nf * 8 + (lane & 3) * 2;
        size_t i0 = ((size_t)b * S_ + q0) * D_ + h * HD_ + n;
        size_t i1 = ((size_t)b * S_ + q0 + 8) * D_ + h * HD_ + n;
        uint32_t h0, l0, h1, l1;
        split2h(oacc[nf][0] * inv0, oacc[nf][1] * inv0, h0, l0);
        split2h(oacc[nf][2] * inv1, oacc[nf][3] * inv1, h1, l1);
        *(uint32_t*)&ctx_hi[i0] = h0; *(uint32_t*)&ctx_lo[i0] = l0;
        *(uint32_t*)&ctx_hi[i1] = h1; *(uint32_t*)&ctx_lo[i1] = l1;
    }

    // ---- tail: rescale own attn tile (reads are L2-warm) ----
    __syncthreads();   // all e writes + sinv visible
    float* arow = attn + ((size_t)ibh * S_ + bq) * S_;
    #pragma unroll 4
    for (int row = 0; row < 128; row++) {
        float inv = sinv[row];
        float4* p = (float4*)(arow + (size_t)row * S_) + tid;
        float4 v = *p;
        v.x *= inv; v.y *= inv; v.z *= inv; v.w *= inv;
        *p = v;
    }
}

// ============================================================================
extern "C" void kernel_launch(void* const* d_in, const int* in_sizes, int n_in,
                              void* d_out, int out_size)
{
    const float* query = (const float*)d_in[0];
    const float* key_  = (const float*)d_in[1];
    const float* value = (const float*)d_in[2];
    const int*   mask  = (const int*)d_in[3];
    const float* Wq = (const float*)d_in[4];  const float* bq = (const float*)d_in[5];
    const float* Wk = (const float*)d_in[6];  const float* bk = (const float*)d_in[7];
    const float* Wv = (const float*)d_in[8];  const float* bv = (const float*)d_in[9];
    const float* Wo = (const float*)d_in[10]; const float* bo = (const float*)d_in[11];
    float* out = (float*)d_out;

    float* pfb;
    __half *pxh, *pxl;
    cudaGetSymbolAddress((void**)&pfb, g_attn_fb);
    cudaGetSymbolAddress((void**)&pxh, g_xh3);
    cudaGetSymbolAddress((void**)&pxl, g_xl3);

    static bool attr_set = false;
    if (!attr_set) {
        cudaFuncSetAttribute(qkv_proj, cudaFuncAttributeMaxDynamicSharedMemorySize, PROJ_SMEM);
        cudaFuncSetAttribute(out_proj, cudaFuncAttributeMaxDynamicSharedMemorySize, PROJ_SMEM);
        cudaFuncSetAttribute(flash_attn, cudaFuncAttributeMaxDynamicSharedMemorySize, FA_SMEM);
        attr_set = true;
    }

    const size_t OUT_E = (size_t)M_ * D_;
    const size_t ATT_E = (size_t)B_ * H_ * S_ * S_;
    float* attn = ((size_t)out_size >= OUT_E + ATT_E) ? (out + OUT_E) : pfb;

    const int NX8 = M_ * D_ / 8;
    const int NW8 = D_ * D_ / 8;

    // 1. Split q/k/v inputs (one launch) + convert all 4 weights (one launch)
    split3_kernel<<<dim3(NX8 / 256, 3), 256>>>(query, key_, value, NX8);
    convw_kernel<<<dim3(NW8 / 256, 4), 256>>>(Wq, Wk, Wv, Wo, NW8);

    // 2. Merged Q/K/V projections (768 CTAs)
    qkv_proj<<<dim3(M_ / 128, D_ / 128, 3), 256, PROJ_SMEM>>>(bq, bk, bv);

    // 3. Fused attention (+ in-kernel attn normalization); ctx -> g_xh3/g_xl3[0]
    flash_attn<<<dim3(S_ / 128, B_ * H_), 256, FA_SMEM>>>(mask, attn, pxh, pxl);

    // 4. Output projection
    out_proj<<<dim3(M_ / 128, D_ / 128), 256, PROJ_SMEM>>>(bo, out);
}

// round 14
// speedup vs baseline: 1.5327x; 1.0332x over previous
#include <cuda_runtime.h>
#include <cuda_fp16.h>
#include <cstdint>

#define B_  4
#define S_  1024
#define D_  1024
#define H_  16
#define HD_ 64
#define M_  (B_*S_)
#define QKV_E ((size_t)B_*H_*S_*HD_)   // 4M elements per tensor

// ---------------- scratch (static __device__, no allocation) ----------------
__device__ float g_attn_fb[(size_t)B_*H_*S_*S_];
__device__ __half g_xh3[3*(size_t)M_*D_];     // split inputs (hi); [0] reused for ctx_hi
__device__ __half g_xl3[3*(size_t)M_*D_];     // split inputs (lo); [0] reused for ctx_lo
__device__ __half g_wh4[4*(size_t)D_*D_];     // Wq,Wk,Wv,Wo hi
__device__ __half g_qkvh[3*QKV_E];            // q,k,v hi (head-split)
__device__ __half g_qkvl[3*QKV_E];            // q,k,v lo

// ================= arch-neutral PTX helpers (sm_80-era only) ================
__device__ __forceinline__ uint32_t smem_u32(const void* p) {
    uint32_t a;
    asm("{ .reg .u64 t; cvta.to.shared.u64 t, %1; cvt.u32.u64 %0, t; }" : "=r"(a) : "l"(p));
    return a;
}
__device__ __forceinline__ void cp_async16(uint32_t sdst, const void* gsrc) {
    asm volatile("cp.async.cg.shared.global [%0], [%1], 16;" :: "r"(sdst), "l"(gsrc) : "memory");
}
__device__ __forceinline__ void cp_commit() {
    asm volatile("cp.async.commit_group;" ::: "memory");
}
template<int N>
__device__ __forceinline__ void cp_wait() {
    asm volatile("cp.async.wait_group %0;" :: "n"(N) : "memory");
}
__device__ __forceinline__ void ldm_x4(uint32_t a, uint32_t& r0, uint32_t& r1,
                                       uint32_t& r2, uint32_t& r3) {
    asm volatile("ldmatrix.sync.aligned.m8n8.x4.shared.b16 {%0,%1,%2,%3}, [%4];"
        : "=r"(r0), "=r"(r1), "=r"(r2), "=r"(r3) : "r"(a));
}
__device__ __forceinline__ void ldm_x4_t(uint32_t a, uint32_t& r0, uint32_t& r1,
                                         uint32_t& r2, uint32_t& r3) {
    asm volatile("ldmatrix.sync.aligned.m8n8.x4.trans.shared.b16 {%0,%1,%2,%3}, [%4];"
        : "=r"(r0), "=r"(r1), "=r"(r2), "=r"(r3) : "r"(a));
}
__device__ __forceinline__ void mma_f16(float* d, const uint32_t* a, const uint32_t* b) {
    asm volatile("mma.sync.aligned.m16n8k16.row.col.f32.f16.f16.f32 "
        "{%0,%1,%2,%3}, {%4,%5,%6,%7}, {%8,%9}, {%0,%1,%2,%3};"
        : "+f"(d[0]), "+f"(d[1]), "+f"(d[2]), "+f"(d[3])
        : "r"(a[0]), "r"(a[1]), "r"(a[2]), "r"(a[3]), "r"(b[0]), "r"(b[1]));
}
__device__ __forceinline__ uint32_t cvt2h(float a, float b) {
    __half2 p; p.x = __float2half_rn(a); p.y = __float2half_rn(b);
    return *(uint32_t*)&p;
}
__device__ __forceinline__ void split2h(float a, float b, uint32_t& hi, uint32_t& lo) {
    __half ha = __float2half_rn(a), hb = __float2half_rn(b);
    __half2 hp; hp.x = ha; hp.y = hb;
    __half2 lp;
    lp.x = __float2half_rn(a - __half2float(ha));
    lp.y = __float2half_rn(b - __half2float(hb));
    hi = *(uint32_t*)&hp; lo = *(uint32_t*)&lp;
}

// ======= merged fp32 -> fp16 hi/lo split for query/key/value (z grid) =======
__global__ void __launch_bounds__(256) split3_kernel(
    const float* __restrict__ q, const float* __restrict__ k,
    const float* __restrict__ v, int n8)
{
    int z = blockIdx.y;
    const float* x = (z == 0) ? q : (z == 1) ? k : v;
    __half* hi = g_xh3 + (size_t)z * M_ * D_;
    __half* lo = g_xl3 + (size_t)z * M_ * D_;
    int i = blockIdx.x * 256 + threadIdx.x;
    if (i >= n8) return;
    float4 v0 = ((const float4*)x)[2*i];
    float4 v1 = ((const float4*)x)[2*i + 1];
    uint4 hv, lv;
    split2h(v0.x, v0.y, hv.x, lv.x);
    split2h(v0.z, v0.w, hv.y, lv.y);
    split2h(v1.x, v1.y, hv.z, lv.z);
    split2h(v1.z, v1.w, hv.w, lv.w);
    ((uint4*)hi)[i] = hv;
    ((uint4*)lo)[i] = lv;
}

// ============ merged weight fp32 -> fp16 convert (4 weights, z grid) ========
__global__ void __launch_bounds__(256) convw_kernel(
    const float* __restrict__ wq, const float* __restrict__ wk,
    const float* __restrict__ wv, const float* __restrict__ wo, int n8)
{
    int z = blockIdx.y;
    const float* x = (z == 0) ? wq : (z == 1) ? wk : (z == 2) ? wv : wo;
    __half* hi = g_wh4 + (size_t)z * D_ * D_;
    int i = blockIdx.x * 256 + threadIdx.x;
    if (i >= n8) return;
    float4 v0 = ((const float4*)x)[2*i];
    float4 v1 = ((const float4*)x)[2*i + 1];
    uint4 hv;
    hv.x = cvt2h(v0.x, v0.y); hv.y = cvt2h(v0.z, v0.w);
    hv.z = cvt2h(v1.x, v1.y); hv.w = cvt2h(v1.z, v1.w);
    ((uint4*)hi)[i] = hv;
}

// ============================================================================
// GEMM core (2-term fp16): shared between qkv_proj (MODE 0, z-merged) and
// out_proj (MODE 1).  CTA 128x128, kChunk=32, 8 warps, double-buffered.
// ============================================================================
#define LDK   40
#define MAT_B (128 * LDK * 2)
#define BUF_B (3 * MAT_B)
#define PROJ_SMEM (2 * BUF_B)

template<int MODE>
__device__ __forceinline__ void proj_body(
    const __half* __restrict__ Xhi, const __half* __restrict__ Xlo,
    const __half* __restrict__ Whi, const float* __restrict__ bias,
    float* __restrict__ Yf, __half* __restrict__ Yh, __half* __restrict__ Yl,
    char* smem)
{
    const int K = D_;
    int tid = threadIdx.x, wid = tid >> 5, lane = tid & 31;
    int bm = blockIdx.x * 128, bn = blockIdx.y * 128;
    int warp_m = (wid & 3) * 32, warp_n = (wid >> 2) * 64;
    uint32_t sbase = smem_u32(smem);

    int lrow = tid >> 1, lcol = (tid & 1) * 16;
    const __half* gA_h = Xhi + (size_t)(bm + lrow) * K + lcol;
    const __half* gA_l = Xlo + (size_t)(bm + lrow) * K + lcol;
    const __half* gB_h = Whi + (size_t)(bn + lrow) * K + lcol;
    uint32_t soff = (uint32_t)(lrow * LDK + lcol) * 2;

    auto issue_chunk = [&](int c, int buf) {
        uint32_t base = sbase + buf * BUF_B;
        int k0 = c * 32;
        #pragma unroll
        for (int h = 0; h < 2; h++) {
            uint32_t so = soff + h * 16;
            int go = k0 + h * 8;
            cp_async16(base + 0*MAT_B + so, gA_h + go);
            cp_async16(base + 1*MAT_B + so, gA_l + go);
            cp_async16(base + 2*MAT_B + so, gB_h + go);
        }
        cp_commit();
    };

    float acc[2][8][4];
    #pragma unroll
    for (int mf = 0; mf < 2; mf++)
        #pragma unroll
        for (int nf = 0; nf < 8; nf++)
            #pragma unroll
            for (int r = 0; r < 4; r++) acc[mf][nf][r] = 0.f;

    const int NCH = K / 32;
    issue_chunk(0, 0);
    int buf = 0;

    uint32_t a_off = (uint32_t)((warp_m + (lane & 15)) * LDK + (lane >> 4) * 8) * 2;
    uint32_t b_off = (uint32_t)((warp_n + ((lane >> 4) * 8) + (lane & 7)) * LDK
                                + (((lane >> 3) & 1) * 8)) * 2;

    for (int c = 0; c < NCH; c++) {
        if (c + 1 < NCH) { issue_chunk(c + 1, buf ^ 1); cp_wait<1>(); }
        else cp_wait<0>();
        __syncthreads();

        uint32_t base = sbase + buf * BUF_B;
        #pragma unroll
        for (int ks = 0; ks < 2; ks++) {
            uint32_t kso = (uint32_t)(ks * 16) * 2;
            uint32_t ah[2][4], al[2][4], bh[8][2];
            #pragma unroll
            for (int mf = 0; mf < 2; mf++) {
                uint32_t ao = a_off + (uint32_t)(mf * 16 * LDK) * 2 + kso;
                ldm_x4(base + 0*MAT_B + ao, ah[mf][0], ah[mf][1], ah[mf][2], ah[mf][3]);
                ldm_x4(base + 1*MAT_B + ao, al[mf][0], al[mf][1], al[mf][2], al[mf][3]);
            }
            #pragma unroll
            for (int bg = 0; bg < 4; bg++) {
                uint32_t bo = b_off + (uint32_t)(bg * 16 * LDK) * 2 + kso;
                ldm_x4(base + 2*MAT_B + bo, bh[bg*2][0], bh[bg*2][1], bh[bg*2+1][0], bh[bg*2+1][1]);
            }
            #pragma unroll
            for (int mf = 0; mf < 2; mf++)
                #pragma unroll
                for (int nf = 0; nf < 8; nf++) {
                    mma_f16(acc[mf][nf], ah[mf], bh[nf]);
                    mma_f16(acc[mf][nf], al[mf], bh[nf]);
                }
        }
        __syncthreads();
        buf ^= 1;
    }

    int g = lane >> 2;
    #pragma unroll
    for (int nf = 0; nf < 8; nf++) {
        int n = bn + warp_n + nf * 8 + (lane & 3) * 2;
        float b0 = bias[n], b1 = bias[n + 1];
        #pragma unroll
        for (int mf = 0; mf < 2; mf++) {
            int m = bm + warp_m + mf * 16 + g;
            float2 o0, o1;
            o0.x = acc[mf][nf][0] + b0; o0.y = acc[mf][nf][1] + b1;
            o1.x = acc[mf][nf][2] + b0; o1.y = acc[mf][nf][3] + b1;
            if (MODE == 0) {
                int bb = m >> 10, s = m & 1023;
                int h = n >> 6, d = n & 63;
                size_t rb = (((size_t)bb * H_ + h) * S_);
                size_t i0 = (rb + s) * HD_ + d;
                size_t i1 = (rb + s + 8) * HD_ + d;
                uint32_t h0, l0, h1, l1;
                split2h(o0.x, o0.y, h0, l0);
                split2h(o1.x, o1.y, h1, l1);
                *(uint32_t*)&Yh[i0] = h0; *(uint32_t*)&Yl[i0] = l0;
                *(uint32_t*)&Yh[i1] = h1; *(uint32_t*)&Yl[i1] = l1;
            } else {
                *(float2*)&Yf[(size_t)m * D_ + n] = o0;
                *(float2*)&Yf[(size_t)(m + 8) * D_ + n] = o1;
            }
        }
    }
}

// Merged Q/K/V projection: z in {0,1,2}
__global__ void __launch_bounds__(256) qkv_proj(
    const float* __restrict__ bq, const float* __restrict__ bk,
    const float* __restrict__ bv)
{
    extern __shared__ char smem[];
    int z = blockIdx.z;
    const float* bias = (z == 0) ? bq : (z == 1) ? bk : bv;
    proj_body<0>(g_xh3 + (size_t)z * M_ * D_, g_xl3 + (size_t)z * M_ * D_,
                 g_wh4 + (size_t)z * D_ * D_, bias, nullptr,
                 g_qkvh + (size_t)z * QKV_E, g_qkvl + (size_t)z * QKV_E, smem);
}

// Output projection: ctx hi/lo live in g_xh3[0]/g_xl3[0]
__global__ void __launch_bounds__(256) out_proj(
    const float* __restrict__ bo, float* __restrict__ out)
{
    extern __shared__ char smem[];
    proj_body<1>(g_xh3, g_xl3, g_wh4 + 3 * (size_t)D_ * D_, bo, out,
                 nullptr, nullptr, smem);
}

// ============================================================================
// Single-pass fused attention + in-kernel tail rescale.  k-chunk = 64,
// double-buffered; 2 CTAs/SM (~97KB smem, <=128 regs).
// ============================================================================
#define FLS 72
#define SQH 0
#define SQL 18432
#define KVB 36864
#define KVMAT 9216                 // one 64-row matrix: 64*144
#define KVSZ (3 * KVMAT)           // KH, VH, VL = 27648
#define SMSK (KVB + 2*KVSZ)        // 92160
#define SINV (SMSK + 4096)         // 96256
#define FA_SMEM (SINV + 512)       // 96768

__global__ void __launch_bounds__(256, 2) flash_attn(
    const int* __restrict__ mask, float* __restrict__ attn,
    __half* __restrict__ ctx_hi, __half* __restrict__ ctx_lo)
{
    extern __shared__ char smem[];
    int ibh = blockIdx.y;
    int b = ibh >> 4, h = ibh & 15;
    int bq = blockIdx.x * 128;
    int tid = threadIdx.x, wid = tid >> 5, lane = tid & 31;
    int wm = wid * 16;
    uint32_t sb = smem_u32(smem);

    const __half* Qh = g_qkvh + ((size_t)ibh * S_ + bq) * HD_;
    const __half* Ql = g_qkvl + ((size_t)ibh * S_ + bq) * HD_;
    const __half* Kh = g_qkvh + QKV_E + (size_t)ibh * S_ * HD_;
    const __half* Vh = g_qkvh + 2 * QKV_E + (size_t)ibh * S_ * HD_;
    const __half* Vl = g_qkvl + 2 * QKV_E + (size_t)ibh * S_ * HD_;
    const int* msk = (const int*)(smem + SMSK);
    float* sinv = (float*)(smem + SINV);

    // group 0: Q tile + mask
    #pragma unroll
    for (int t = 0; t < 4; t++) {
        int idx = tid + t * 256;
        int row = idx >> 3, pc = idx & 7;
        uint32_t so = (uint32_t)(row * FLS + pc * 8) * 2;
        size_t go = (size_t)row * HD_ + pc * 8;
        cp_async16(sb + SQH + so, Qh + go);
        cp_async16(sb + SQL + so, Ql + go);
    }
    cp_async16(sb + SMSK + tid * 16, mask + (size_t)b * S_ + tid * 4);
    cp_commit();

    // 64-row KV chunk loader (2 cp.async per mat per thread)
    auto issue_kv = [&](int c, int buf) {
        uint32_t base = sb + KVB + buf * KVSZ;
        int k0 = c * 64;
        #pragma unroll
        for (int t = 0; t < 2; t++) {
            int idx = tid + t * 256;
            int row = idx >> 3, pc = idx & 7;
            uint32_t so = (uint32_t)(row * FLS + pc * 8) * 2;
            size_t go = (size_t)(k0 + row) * HD_ + pc * 8;
            cp_async16(base + 0*KVMAT + so, Kh + go);
            cp_async16(base + 1*KVMAT + so, Vh + go);
            cp_async16(base + 2*KVMAT + so, Vl + go);
        }
        cp_commit();
    };

    uint32_t a_off = (uint32_t)((wm + (lane & 15)) * FLS + (lane >> 4) * 8) * 2;
    uint32_t b_off = (uint32_t)((((lane >> 4) * 8) + (lane & 7)) * FLS
                                + (((lane >> 3) & 1) * 8)) * 2;
    uint32_t v_off = (uint32_t)((lane & 15) * FLS + (lane >> 4) * 8) * 2;

    issue_kv(0, 0);

    float lsum0 = 0.f, lsum1 = 0.f;
    float oacc[8][4];
    #pragma unroll
    for (int nf = 0; nf < 8; nf++)
        #pragma unroll
        for (int r = 0; r < 4; r++) oacc[nf][r] = 0.f;

    cp_wait<1>();
    __syncthreads();
    uint32_t qfh[4][4], qfl[4][4];
    #pragma unroll
    for (int ks = 0; ks < 4; ks++) {
        uint32_t ao = a_off + (uint32_t)(ks * 32);
        ldm_x4(sb + SQH + ao, qfh[ks][0], qfh[ks][1], qfh[ks][2], qfh[ks][3]);
        ldm_x4(sb + SQL + ao, qfl[ks][0], qfl[ks][1], qfl[ks][2], qfl[ks][3]);
    }

    int g = lane >> 2;
    int q0 = bq + wm + g;

    for (int c = 0; c < 16; c++) {
        if (c < 15) { issue_kv(c + 1, (c + 1) & 1); cp_wait<1>(); }
        else cp_wait<0>();
        __syncthreads();

        uint32_t kvb = sb + KVB + (c & 1) * KVSZ;
        int ck = c * 64;

        // ---- S = (Qh+Ql)@Kh^T over 64 K rows (8 n-frags) ----
        float sf[8][4];
        #pragma unroll
        for (int j = 0; j < 8; j++)
            #pragma unroll
            for (int r = 0; r < 4; r++) sf[j][r] = 0.f;
        #pragma unroll
        for (int ks = 0; ks < 4; ks++) {
            #pragma unroll
            for (int bg = 0; bg < 4; bg++) {
                uint32_t khf[2][2];
                uint32_t bo = b_off + (uint32_t)(bg * 16 * FLS) * 2 + (uint32_t)(ks * 32);
                ldm_x4(kvb + bo, khf[0][0], khf[0][1], khf[1][0], khf[1][1]);
                mma_f16(sf[bg*2],   qfh[ks], khf[0]);
                mma_f16(sf[bg*2],   qfl[ks], khf[0]);
                mma_f16(sf[bg*2+1], qfh[ks], khf[1]);
                mma_f16(sf[bg*2+1], qfl[ks], khf[1]);
            }
        }

        // ---- mask/scale, exp, l accumulate, unnormalized attn write ----
        #pragma unroll
        for (int j = 0; j < 8; j++) {
            int n = ck + j * 8 + (lane & 3) * 2;
            int mk0 = msk[n], mk1 = msk[n + 1];
            float e0 = mk0 ? __expf(sf[j][0] * 0.125f) : 0.f;
            float e1 = mk1 ? __expf(sf[j][1] * 0.125f) : 0.f;
            float e2 = mk0 ? __expf(sf[j][2] * 0.125f) : 0.f;
            float e3 = mk1 ? __expf(sf[j][3] * 0.125f) : 0.f;
            lsum0 += e0 + e1; lsum1 += e2 + e3;
            sf[j][0] = e0; sf[j][1] = e1; sf[j][2] = e2; sf[j][3] = e3;
            float2 w0; w0.x = e0; w0.y = e1;
            float2 w1; w1.x = e2; w1.y = e3;
            *(float2*)&attn[((size_t)ibh * S_ + q0) * S_ + n] = w0;
            *(float2*)&attn[((size_t)ibh * S_ + q0 + 8) * S_ + n] = w1;
        }

        // ---- O += Eh @ (Vh + Vl) over 64 k rows (4 ks groups) ----
        #pragma unroll
        for (int ks = 0; ks < 4; ks++) {
            uint32_t pah[4];
            pah[0] = cvt2h(sf[2*ks][0],   sf[2*ks][1]);
            pah[1] = cvt2h(sf[2*ks][2],   sf[2*ks][3]);
            pah[2] = cvt2h(sf[2*ks+1][0], sf[2*ks+1][1]);
            pah[3] = cvt2h(sf[2*ks+1][2], sf[2*ks+1][3]);
            uint32_t bvh[8][2], bvl[8][2];
            #pragma unroll
            for (int ng = 0; ng < 4; ng++) {
                uint32_t vo = v_off + (uint32_t)(ks * 16 * FLS) * 2 + (uint32_t)(ng * 16) * 2;
                ldm_x4_t(kvb + 1*KVMAT + vo, bvh[ng*2][0], bvh[ng*2][1], bvh[ng*2+1][0], bvh[ng*2+1][1]);
                ldm_x4_t(kvb + 2*KVMAT + vo, bvl[ng*2][0], bvl[ng*2][1], bvl[ng*2+1][0], bvl[ng*2+1][1]);
            }
            #pragma unroll
            for (int nf = 0; nf < 8; nf++) {
                mma_f16(oacc[nf], pah, bvh[nf]);
                mma_f16(oacc[nf], pah, bvl[nf]);
            }
        }
        __syncthreads();
    }

    // ---- finalize: reduce l, publish 1/l, write ctx ----
    lsum0 += __shfl_xor_sync(0xffffffffu, lsum0, 1);
    lsum0 += __shfl_xor_sync(0xffffffffu, lsum0, 2);
    lsum1 += __shfl_xor_sync(0xffffffffu, lsum1, 1);
    lsum1 += __shfl_xor_sync(0xffffffffu, lsum1, 2);
    float inv0 = 1.f / lsum0, inv1 = 1.f / lsum1;
    if ((lane & 3) == 0) {
        sinv[wm + g] = inv0;
        sinv[wm + g + 8] = inv1;
    }
    #pragma unroll
    for (int nf = 0; nf < 8; nf++) {
        int n = nf * 8 + (lane & 3) * 2;
        size_t i0 = ((size_t)b * S_ + q0) * D_ + h * HD_ + n;
        size_t i1 = ((size_t)b * S_ + q0 + 8) * D_ + h * HD_ + n;
        uint32_t h0, l0, h1, l1;
        split2h(oacc[nf][0] * inv0, oacc[nf][1] * inv0, h0, l0);
        split2h(oacc[nf][2] * inv1, oacc[nf][3] * inv1, h1, l1);
        *(uint32_t*)&ctx_hi[i0] = h0; *(uint32_t*)&ctx_lo[i0] = l0;
        *(uint32_t*)&ctx_hi[i1] = h1; *(uint32_t*)&ctx_lo[i1] = l1;
    }

    // ---- tail: rescale own attn tile ----
    __syncthreads();
    float* arow = attn + ((size_t)ibh * S_ + bq) * S_;
    #pragma unroll 4
    for (int row = 0; row < 128; row++) {
        float inv = sinv[row];
        float4* p = (float4*)(arow + (size_t)row * S_) + tid;
        float4 v = *p;
        v.x *= inv; v.y *= inv; v.z *= inv; v.w *= inv;
        *p = v;
    }
}

// ============================================================================
extern "C" void kernel_launch(void* const* d_in, const int* in_sizes, int n_in,
                              void* d_out, int out_size)
{
    const float* query = (const float*)d_in[0];
    const float* key_  = (const float*)d_in[1];
    const float* value = (const float*)d_in[2];
    const int*   mask  = (const int*)d_in[3];
    const float* Wq = (const float*)d_in[4];  const float* bq = (const float*)d_in[5];
    const float* Wk = (const float*)d_in[6];  const float* bk = (const float*)d_in[7];
    const float* Wv = (const float*)d_in[8];  const float* bv = (const float*)d_in[9];
    const float* Wo = (const float*)d_in[10]; const float* bo = (const float*)d_in[11];
    float* out = (float*)d_out;

    float* pfb;
    __half *pxh, *pxl;
    cudaGetSymbolAddress((void**)&pfb, g_attn_fb);
    cudaGetSymbolAddress((void**)&pxh, g_xh3);
    cudaGetSymbolAddress((void**)&pxl, g_xl3);

    static bool attr_set = false;
    if (!attr_set) {
        cudaFuncSetAttribute(qkv_proj, cudaFuncAttributeMaxDynamicSharedMemorySize, PROJ_SMEM);
        cudaFuncSetAttribute(out_proj, cudaFuncAttributeMaxDynamicSharedMemorySize, PROJ_SMEM);
        cudaFuncSetAttribute(flash_attn, cudaFuncAttributeMaxDynamicSharedMemorySize, FA_SMEM);
        attr_set = true;
    }

    const size_t OUT_E = (size_t)M_ * D_;
    const size_t ATT_E = (size_t)B_ * H_ * S_ * S_;
    float* attn = ((size_t)out_size >= OUT_E + ATT_E) ? (out + OUT_E) : pfb;

    const int NX8 = M_ * D_ / 8;
    const int NW8 = D_ * D_ / 8;

    // 1. Split q/k/v inputs + convert all 4 weights
    split3_kernel<<<dim3(NX8 / 256, 3), 256>>>(query, key_, value, NX8);
    convw_kernel<<<dim3(NW8 / 256, 4), 256>>>(Wq, Wk, Wv, Wo, NW8);

    // 2. Merged Q/K/V projections
    qkv_proj<<<dim3(M_ / 128, D_ / 128, 3), 256, PROJ_SMEM>>>(bq, bk, bv);

    // 3. Fused attention (+ tail rescale); ctx -> g_xh3/g_xl3[0]
    flash_attn<<<dim3(S_ / 128, B_ * H_), 256, FA_SMEM>>>(mask, attn, pxh, pxl);

    // 4. Output projection
    out_proj<<<dim3(M_ / 128, D_ / 128), 256, PROJ_SMEM>>>(bo, out);
}

// round 16
// speedup vs baseline: 1.5803x; 1.0311x over previous
#include <cuda_runtime.h>
#include <cuda_fp16.h>
#include <cstdint>

#define B_  4
#define S_  1024
#define D_  1024
#define H_  16
#define HD_ 64
#define M_  (B_*S_)
#define QKV_E ((size_t)B_*H_*S_*HD_)   // 4M elements per tensor

// ---------------- scratch (static __device__, no allocation) ----------------
__device__ float g_attn_fb[(size_t)B_*H_*S_*S_];
__device__ __half g_xh3[3*(size_t)M_*D_];     // split inputs (hi); [0] reused for ctx_hi
__device__ __half g_xl3[3*(size_t)M_*D_];     // split inputs (lo); [0] reused for ctx_lo
__device__ __half g_wh4[4*(size_t)D_*D_];     // Wq,Wk,Wv,Wo hi
__device__ __half g_qkvh[3*QKV_E];            // q,k,v hi (head-split)
__device__ __half g_qkvl[3*QKV_E];            // q,k,v lo (v lo unused by flash)

// ================= arch-neutral PTX helpers (sm_80-era only) ================
__device__ __forceinline__ uint32_t smem_u32(const void* p) {
    uint32_t a;
    asm("{ .reg .u64 t; cvta.to.shared.u64 t, %1; cvt.u32.u64 %0, t; }" : "=r"(a) : "l"(p));
    return a;
}
__device__ __forceinline__ void cp_async16(uint32_t sdst, const void* gsrc) {
    asm volatile("cp.async.cg.shared.global [%0], [%1], 16;" :: "r"(sdst), "l"(gsrc) : "memory");
}
__device__ __forceinline__ void cp_commit() {
    asm volatile("cp.async.commit_group;" ::: "memory");
}
template<int N>
__device__ __forceinline__ void cp_wait() {
    asm volatile("cp.async.wait_group %0;" :: "n"(N) : "memory");
}
__device__ __forceinline__ void ldm_x4(uint32_t a, uint32_t& r0, uint32_t& r1,
                                       uint32_t& r2, uint32_t& r3) {
    asm volatile("ldmatrix.sync.aligned.m8n8.x4.shared.b16 {%0,%1,%2,%3}, [%4];"
        : "=r"(r0), "=r"(r1), "=r"(r2), "=r"(r3) : "r"(a));
}
__device__ __forceinline__ void ldm_x4_t(uint32_t a, uint32_t& r0, uint32_t& r1,
                                         uint32_t& r2, uint32_t& r3) {
    asm volatile("ldmatrix.sync.aligned.m8n8.x4.trans.shared.b16 {%0,%1,%2,%3}, [%4];"
        : "=r"(r0), "=r"(r1), "=r"(r2), "=r"(r3) : "r"(a));
}
__device__ __forceinline__ void mma_f16(float* d, const uint32_t* a, const uint32_t* b) {
    asm volatile("mma.sync.aligned.m16n8k16.row.col.f32.f16.f16.f32 "
        "{%0,%1,%2,%3}, {%4,%5,%6,%7}, {%8,%9}, {%0,%1,%2,%3};"
        : "+f"(d[0]), "+f"(d[1]), "+f"(d[2]), "+f"(d[3])
        : "r"(a[0]), "r"(a[1]), "r"(a[2]), "r"(a[3]), "r"(b[0]), "r"(b[1]));
}
__device__ __forceinline__ uint32_t cvt2h(float a, float b) {
    __half2 p; p.x = __float2half_rn(a); p.y = __float2half_rn(b);
    return *(uint32_t*)&p;
}
__device__ __forceinline__ void split2h(float a, float b, uint32_t& hi, uint32_t& lo) {
    __half ha = __float2half_rn(a), hb = __float2half_rn(b);
    __half2 hp; hp.x = ha; hp.y = hb;
    __half2 lp;
    lp.x = __float2half_rn(a - __half2float(ha));
    lp.y = __float2half_rn(b - __half2float(hb));
    hi = *(uint32_t*)&hp; lo = *(uint32_t*)&lp;
}

// ======= merged fp32 -> fp16 hi/lo split for query/key/value (z grid) =======
__global__ void __launch_bounds__(256) split3_kernel(
    const float* __restrict__ q, const float* __restrict__ k,
    const float* __restrict__ v, int n8)
{
    int z = blockIdx.y;
    const float* x = (z == 0) ? q : (z == 1) ? k : v;
    __half* hi = g_xh3 + (size_t)z * M_ * D_;
    __half* lo = g_xl3 + (size_t)z * M_ * D_;
    int i = blockIdx.x * 256 + threadIdx.x;
    if (i >= n8) return;
    float4 v0 = ((const float4*)x)[2*i];
    float4 v1 = ((const float4*)x)[2*i + 1];
    uint4 hv, lv;
    split2h(v0.x, v0.y, hv.x, lv.x);
    split2h(v0.z, v0.w, hv.y, lv.y);
    split2h(v1.x, v1.y, hv.z, lv.z);
    split2h(v1.z, v1.w, hv.w, lv.w);
    ((uint4*)hi)[i] = hv;
    ((uint4*)lo)[i] = lv;
}

// ============ merged weight fp32 -> fp16 convert (4 weights, z grid) ========
__global__ void __launch_bounds__(256) convw_kernel(
    const float* __restrict__ wq, const float* __restrict__ wk,
    const float* __restrict__ wv, const float* __restrict__ wo, int n8)
{
    int z = blockIdx.y;
    const float* x = (z == 0) ? wq : (z == 1) ? wk : (z == 2) ? wv : wo;
    __half* hi = g_wh4 + (size_t)z * D_ * D_;
    int i = blockIdx.x * 256 + threadIdx.x;
    if (i >= n8) return;
    float4 v0 = ((const float4*)x)[2*i];
    float4 v1 = ((const float4*)x)[2*i + 1];
    uint4 hv;
    hv.x = cvt2h(v0.x, v0.y); hv.y = cvt2h(v0.z, v0.w);
    hv.z = cvt2h(v1.x, v1.y); hv.w = cvt2h(v1.z, v1.w);
    ((uint4*)hi)[i] = hv;
}

// ============================================================================
// GEMM core (2-term fp16): shared between qkv_proj (MODE 0, z-merged) and
// out_proj (MODE 1).  CTA 128x128, kChunk=32, 8 warps, double-buffered.
// ============================================================================
#define LDK   40
#define MAT_B (128 * LDK * 2)
#define BUF_B (3 * MAT_B)
#define PROJ_SMEM (2 * BUF_B)

template<int MODE>
__device__ __forceinline__ void proj_body(
    const __half* __restrict__ Xhi, const __half* __restrict__ Xlo,
    const __half* __restrict__ Whi, const float* __restrict__ bias,
    float* __restrict__ Yf, __half* __restrict__ Yh, __half* __restrict__ Yl,
    char* smem)
{
    const int K = D_;
    int tid = threadIdx.x, wid = tid >> 5, lane = tid & 31;
    int bm = blockIdx.x * 128, bn = blockIdx.y * 128;
    int warp_m = (wid & 3) * 32, warp_n = (wid >> 2) * 64;
    uint32_t sbase = smem_u32(smem);

    int lrow = tid >> 1, lcol = (tid & 1) * 16;
    const __half* gA_h = Xhi + (size_t)(bm + lrow) * K + lcol;
    const __half* gA_l = Xlo + (size_t)(bm + lrow) * K + lcol;
    const __half* gB_h = Whi + (size_t)(bn + lrow) * K + lcol;
    uint32_t soff = (uint32_t)(lrow * LDK + lcol) * 2;

    auto issue_chunk = [&](int c, int buf) {
        uint32_t base = sbase + buf * BUF_B;
        int k0 = c * 32;
        #pragma unroll
        for (int h = 0; h < 2; h++) {
            uint32_t so = soff + h * 16;
            int go = k0 + h * 8;
            cp_async16(base + 0*MAT_B + so, gA_h + go);
            cp_async16(base + 1*MAT_B + so, gA_l + go);
            cp_async16(base + 2*MAT_B + so, gB_h + go);
        }
        cp_commit();
    };

    float acc[2][8][4];
    #pragma unroll
    for (int mf = 0; mf < 2; mf++)
        #pragma unroll
        for (int nf = 0; nf < 8; nf++)
            #pragma unroll
            for (int r = 0; r < 4; r++) acc[mf][nf][r] = 0.f;

    const int NCH = K / 32;
    issue_chunk(0, 0);
    int buf = 0;

    uint32_t a_off = (uint32_t)((warp_m + (lane & 15)) * LDK + (lane >> 4) * 8) * 2;
    uint32_t b_off = (uint32_t)((warp_n + ((lane >> 4) * 8) + (lane & 7)) * LDK
                                + (((lane >> 3) & 1) * 8)) * 2;

    for (int c = 0; c < NCH; c++) {
        if (c + 1 < NCH) { issue_chunk(c + 1, buf ^ 1); cp_wait<1>(); }
        else cp_wait<0>();
        __syncthreads();

        uint32_t base = sbase + buf * BUF_B;
        #pragma unroll
        for (int ks = 0; ks < 2; ks++) {
            uint32_t kso = (uint32_t)(ks * 16) * 2;
            uint32_t ah[2][4], al[2][4], bh[8][2];
            #pragma unroll
            for (int mf = 0; mf < 2; mf++) {
                uint32_t ao = a_off + (uint32_t)(mf * 16 * LDK) * 2 + kso;
                ldm_x4(base + 0*MAT_B + ao, ah[mf][0], ah[mf][1], ah[mf][2], ah[mf][3]);
                ldm_x4(base + 1*MAT_B + ao, al[mf][0], al[mf][1], al[mf][2], al[mf][3]);
            }
            #pragma unroll
            for (int bg = 0; bg < 4; bg++) {
                uint32_t bo = b_off + (uint32_t)(bg * 16 * LDK) * 2 + kso;
                ldm_x4(base + 2*MAT_B + bo, bh[bg*2][0], bh[bg*2][1], bh[bg*2+1][0], bh[bg*2+1][1]);
            }
            #pragma unroll
            for (int mf = 0; mf < 2; mf++)
                #pragma unroll
                for (int nf = 0; nf < 8; nf++) {
                    mma_f16(acc[mf][nf], ah[mf], bh[nf]);
                    mma_f16(acc[mf][nf], al[mf], bh[nf]);
                }
        }
        __syncthreads();
        buf ^= 1;
    }

    int g = lane >> 2;
    #pragma unroll
    for (int nf = 0; nf < 8; nf++) {
        int n = bn + warp_n + nf * 8 + (lane & 3) * 2;
        float b0 = bias[n], b1 = bias[n + 1];
        #pragma unroll
        for (int mf = 0; mf < 2; mf++) {
            int m = bm + warp_m + mf * 16 + g;
            float2 o0, o1;
            o0.x = acc[mf][nf][0] + b0; o0.y = acc[mf][nf][1] + b1;
            o1.x = acc[mf][nf][2] + b0; o1.y = acc[mf][nf][3] + b1;
            if (MODE == 0) {
                int bb = m >> 10, s = m & 1023;
                int h = n >> 6, d = n & 63;
                size_t rb = (((size_t)bb * H_ + h) * S_);
                size_t i0 = (rb + s) * HD_ + d;
                size_t i1 = (rb + s + 8) * HD_ + d;
                uint32_t h0, l0, h1, l1;
                split2h(o0.x, o0.y, h0, l0);
                split2h(o1.x, o1.y, h1, l1);
                *(uint32_t*)&Yh[i0] = h0; *(uint32_t*)&Yl[i0] = l0;
                *(uint32_t*)&Yh[i1] = h1; *(uint32_t*)&Yl[i1] = l1;
            } else {
                *(float2*)&Yf[(size_t)m * D_ + n] = o0;
                *(float2*)&Yf[(size_t)(m + 8) * D_ + n] = o1;
            }
        }
    }
}

// Merged Q/K/V projection: z in {0,1,2}
__global__ void __launch_bounds__(256) qkv_proj(
    const float* __restrict__ bq, const float* __restrict__ bk,
    const float* __restrict__ bv)
{
    extern __shared__ char smem[];
    int z = blockIdx.z;
    const float* bias = (z == 0) ? bq : (z == 1) ? bk : bv;
    proj_body<0>(g_xh3 + (size_t)z * M_ * D_, g_xl3 + (size_t)z * M_ * D_,
                 g_wh4 + (size_t)z * D_ * D_, bias, nullptr,
                 g_qkvh + (size_t)z * QKV_E, g_qkvl + (size_t)z * QKV_E, smem);
}

// Output projection: ctx hi/lo live in g_xh3[0]/g_xl3[0]
__global__ void __launch_bounds__(256) out_proj(
    const float* __restrict__ bo, float* __restrict__ out)
{
    extern __shared__ char smem[];
    proj_body<1>(g_xh3, g_xl3, g_wh4 + 3 * (size_t)D_ * D_, bo, out,
                 nullptr, nullptr, smem);
}

// ============================================================================
// Single-pass fused attention + tail rescale.  k-chunk = 64, double-buffered,
// 2 CTAs/SM (~78KB smem).  P@V is single-term (Eh @ Vh): V-lo dropped —
// error lands only on the out-path which has margin vs the attn-path.
// ============================================================================
#define FLS 72
#define SQH 0
#define SQL 18432
#define KVB 36864
#define KVMAT 9216                 // one 64-row matrix: 64*144
#define KVSZ (2 * KVMAT)           // KH, VH = 18432
#define SMSK (KVB + 2*KVSZ)        // 73728
#define SINV (SMSK + 4096)         // 77824
#define FA_SMEM (SINV + 512)       // 78336

__global__ void __launch_bounds__(256, 2) flash_attn(
    const int* __restrict__ mask, float* __restrict__ attn,
    __half* __restrict__ ctx_hi, __half* __restrict__ ctx_lo)
{
    extern __shared__ char smem[];
    int ibh = blockIdx.y;
    int b = ibh >> 4, h = ibh & 15;
    int bq = blockIdx.x * 128;
    int tid = threadIdx.x, wid = tid >> 5, lane = tid & 31;
    int wm = wid * 16;
    uint32_t sb = smem_u32(smem);

    const __half* Qh = g_qkvh + ((size_t)ibh * S_ + bq) * HD_;
    const __half* Ql = g_qkvl + ((size_t)ibh * S_ + bq) * HD_;
    const __half* Kh = g_qkvh + QKV_E + (size_t)ibh * S_ * HD_;
    const __half* Vh = g_qkvh + 2 * QKV_E + (size_t)ibh * S_ * HD_;
    const int* msk = (const int*)(smem + SMSK);
    float* sinv = (float*)(smem + SINV);

    // group 0: Q tile + mask
    #pragma unroll
    for (int t = 0; t < 4; t++) {
        int idx = tid + t * 256;
        int row = idx >> 3, pc = idx & 7;
        uint32_t so = (uint32_t)(row * FLS + pc * 8) * 2;
        size_t go = (size_t)row * HD_ + pc * 8;
        cp_async16(sb + SQH + so, Qh + go);
        cp_async16(sb + SQL + so, Ql + go);
    }
    cp_async16(sb + SMSK + tid * 16, mask + (size_t)b * S_ + tid * 4);
    cp_commit();

    // 64-row KV chunk loader: K hi + V hi only
    auto issue_kv = [&](int c, int buf) {
        uint32_t base = sb + KVB + buf * KVSZ;
        int k0 = c * 64;
        #pragma unroll
        for (int t = 0; t < 2; t++) {
            int idx = tid + t * 256;
            int row = idx >> 3, pc = idx & 7;
            uint32_t so = (uint32_t)(row * FLS + pc * 8) * 2;
            size_t go = (size_t)(k0 + row) * HD_ + pc * 8;
            cp_async16(base + 0*KVMAT + so, Kh + go);
            cp_async16(base + 1*KVMAT + so, Vh + go);
        }
        cp_commit();
    };

    uint32_t a_off = (uint32_t)((wm + (lane & 15)) * FLS + (lane >> 4) * 8) * 2;
    uint32_t b_off = (uint32_t)((((lane >> 4) * 8) + (lane & 7)) * FLS
                                + (((lane >> 3) & 1) * 8)) * 2;
    uint32_t v_off = (uint32_t)((lane & 15) * FLS + (lane >> 4) * 8) * 2;

    issue_kv(0, 0);

    float lsum0 = 0.f, lsum1 = 0.f;
    float oacc[8][4];
    #pragma unroll
    for (int nf = 0; nf < 8; nf++)
        #pragma unroll
        for (int r = 0; r < 4; r++) oacc[nf][r] = 0.f;

    cp_wait<1>();
    __syncthreads();
    uint32_t qfh[4][4], qfl[4][4];
    #pragma unroll
    for (int ks = 0; ks < 4; ks++) {
        uint32_t ao = a_off + (uint32_t)(ks * 32);
        ldm_x4(sb + SQH + ao, qfh[ks][0], qfh[ks][1], qfh[ks][2], qfh[ks][3]);
        ldm_x4(sb + SQL + ao, qfl[ks][0], qfl[ks][1], qfl[ks][2], qfl[ks][3]);
    }

    int g = lane >> 2;
    int q0 = bq + wm + g;

    for (int c = 0; c < 16; c++) {
        if (c < 15) { issue_kv(c + 1, (c + 1) & 1); cp_wait<1>(); }
        else cp_wait<0>();
        __syncthreads();

        uint32_t kvb = sb + KVB + (c & 1) * KVSZ;
        int ck = c * 64;

        // ---- S = (Qh+Ql)@Kh^T over 64 K rows ----
        float sf[8][4];
        #pragma unroll
        for (int j = 0; j < 8; j++)
            #pragma unroll
            for (int r = 0; r < 4; r++) sf[j][r] = 0.f;
        #pragma unroll
        for (int ks = 0; ks < 4; ks++) {
            #pragma unroll
            for (int bg = 0; bg < 4; bg++) {
                uint32_t khf[2][2];
                uint32_t bo = b_off + (uint32_t)(bg * 16 * FLS) * 2 + (uint32_t)(ks * 32);
                ldm_x4(kvb + bo, khf[0][0], khf[0][1], khf[1][0], khf[1][1]);
                mma_f16(sf[bg*2],   qfh[ks], khf[0]);
                mma_f16(sf[bg*2],   qfl[ks], khf[0]);
                mma_f16(sf[bg*2+1], qfh[ks], khf[1]);
                mma_f16(sf[bg*2+1], qfl[ks], khf[1]);
            }
        }

        // ---- mask/scale, exp, l accumulate, unnormalized attn write ----
        #pragma unroll
        for (int j = 0; j < 8; j++) {
            int n = ck + j * 8 + (lane & 3) * 2;
            int mk0 = msk[n], mk1 = msk[n + 1];
            float e0 = mk0 ? __expf(sf[j][0] * 0.125f) : 0.f;
            float e1 = mk1 ? __expf(sf[j][1] * 0.125f) : 0.f;
            float e2 = mk0 ? __expf(sf[j][2] * 0.125f) : 0.f;
            float e3 = mk1 ? __expf(sf[j][3] * 0.125f) : 0.f;
            lsum0 += e0 + e1; lsum1 += e2 + e3;
            sf[j][0] = e0; sf[j][1] = e1; sf[j][2] = e2; sf[j][3] = e3;
            float2 w0; w0.x = e0; w0.y = e1;
            float2 w1; w1.x = e2; w1.y = e3;
            *(float2*)&attn[((size_t)ibh * S_ + q0) * S_ + n] = w0;
            *(float2*)&attn[((size_t)ibh * S_ + q0 + 8) * S_ + n] = w1;
        }

        // ---- O += Eh @ Vh (single-term) ----
        #pragma unroll
        for (int ks = 0; ks < 4; ks++) {
            uint32_t pah[4];
            pah[0] = cvt2h(sf[2*ks][0],   sf[2*ks][1]);
            pah[1] = cvt2h(sf[2*ks][2],   sf[2*ks][3]);
            pah[2] = cvt2h(sf[2*ks+1][0], sf[2*ks+1][1]);
            pah[3] = cvt2h(sf[2*ks+1][2], sf[2*ks+1][3]);
            uint32_t bvh[8][2];
            #pragma unroll
            for (int ng = 0; ng < 4; ng++) {
                uint32_t vo = v_off + (uint32_t)(ks * 16 * FLS) * 2 + (uint32_t)(ng * 16) * 2;
                ldm_x4_t(kvb + 1*KVMAT + vo, bvh[ng*2][0], bvh[ng*2][1], bvh[ng*2+1][0], bvh[ng*2+1][1]);
            }
            #pragma unroll
            for (int nf = 0; nf < 8; nf++)
                mma_f16(oacc[nf], pah, bvh[nf]);
        }
        __syncthreads();
    }

    // ---- finalize: reduce l, publish 1/l, write ctx ----
    lsum0 += __shfl_xor_sync(0xffffffffu, lsum0, 1);
    lsum0 += __shfl_xor_sync(0xffffffffu, lsum0, 2);
    lsum1 += __shfl_xor_sync(0xffffffffu, lsum1, 1);
    lsum1 += __shfl_xor_sync(0xffffffffu, lsum1, 2);
    float inv0 = 1.f / lsum0, inv1 = 1.f / lsum1;
    if ((lane & 3) == 0) {
        sinv[wm + g] = inv0;
        sinv[wm + g + 8] = inv1;
    }
    #pragma unroll
    for (int nf = 0; nf < 8; nf++) {
        int n = nf * 8 + (lane & 3) * 2;
        size_t i0 = ((size_t)b * S_ + q0) * D_ + h * HD_ + n;
        size_t i1 = ((size_t)b * S_ + q0 + 8) * D_ + h * HD_ + n;
        uint32_t h0, l0, h1, l1;
        split2h(oacc[nf][0] * inv0, oacc[nf][1] * inv0, h0, l0);
        split2h(oacc[nf][2] * inv1, oacc[nf][3] * inv1, h1, l1);
        *(uint32_t*)&ctx_hi[i0] = h0; *(uint32_t*)&ctx_lo[i0] = l0;
        *(uint32_t*)&ctx_hi[i1] = h1; *(uint32_t*)&ctx_lo[i1] = l1;
    }

    // ---- tail: rescale own attn tile ----
    __syncthreads();
    float* arow = attn + ((size_t)ibh * S_ + bq) * S_;
    #pragma unroll 4
    for (int row = 0; row < 128; row++) {
        float inv = sinv[row];
        float4* p = (float4*)(arow + (size_t)row * S_) + tid;
        float4 v = *p;
        v.x *= inv; v.y *= inv; v.z *= inv; v.w *= inv;
        *p = v;
    }
}

// ============================================================================
extern "C" void kernel_launch(void* const* d_in, const int* in_sizes, int n_in,
                              void* d_out, int out_size)
{
    const float* query = (const float*)d_in[0];
    const float* key_  = (const float*)d_in[1];
    const float* value = (const float*)d_in[2];
    const int*   mask  = (const int*)d_in[3];
    const float* Wq = (const float*)d_in[4];  const float* bq = (const float*)d_in[5];
    const float* Wk = (const float*)d_in[6];  const float* bk = (const float*)d_in[7];
    const float* Wv = (const float*)d_in[8];  const float* bv = (const float*)d_in[9];
    const float* Wo = (const float*)d_in[10]; const float* bo = (const float*)d_in[11];
    float* out = (float*)d_out;

    float* pfb;
    __half *pxh, *pxl;
    cudaGetSymbolAddress((void**)&pfb, g_attn_fb);
    cudaGetSymbolAddress((void**)&pxh, g_xh3);
    cudaGetSymbolAddress((void**)&pxl, g_xl3);

    static bool attr_set = false;
    if (!attr_set) {
        cudaFuncSetAttribute(qkv_proj, cudaFuncAttributeMaxDynamicSharedMemorySize, PROJ_SMEM);
        cudaFuncSetAttribute(out_proj, cudaFuncAttributeMaxDynamicSharedMemorySize, PROJ_SMEM);
        cudaFuncSetAttribute(flash_attn, cudaFuncAttributeMaxDynamicSharedMemorySize, FA_SMEM);
        attr_set = true;
    }

    const size_t OUT_E = (size_t)M_ * D_;
    const size_t ATT_E = (size_t)B_ * H_ * S_ * S_;
    float* attn = ((size_t)out_size >= OUT_E + ATT_E) ? (out + OUT_E) : pfb;

    const int NX8 = M_ * D_ / 8;
    const int NW8 = D_ * D_ / 8;

    // 1. Split q/k/v inputs + convert all 4 weights
    split3_kernel<<<dim3(NX8 / 256, 3), 256>>>(query, key_, value, NX8);
    convw_kernel<<<dim3(NW8 / 256, 4), 256>>>(Wq, Wk, Wv, Wo, NW8);

    // 2. Merged Q/K/V projections
    qkv_proj<<<dim3(M_ / 128, D_ / 128, 3), 256, PROJ_SMEM>>>(bq, bk, bv);

    // 3. Fused attention (+ tail rescale); ctx -> g_xh3/g_xl3[0]
    flash_attn<<<dim3(S_ / 128, B_ * H_), 256, FA_SMEM>>>(mask, attn, pxh, pxl);

    // 4. Output projection
    out_proj<<<dim3(M_ / 128, D_ / 128), 256, PROJ_SMEM>>>(bo, out);
}